// round 6
// baseline (speedup 1.0000x reference)
#include <cuda_runtime.h>

// ChannelLinearAttention, B=16, C=512, W=H=64 (N=4096), fp32.
//
// Decomposition:
//   rnorm[b,n]  = 1/||x[b,:,n]||_2
//   colsum[b,n] = sum_c x[b,c,n]
//   w[b,n]      = rnorm*(colsum*rnorm + eps)
//   tailor[b,c] = 1/(N + sum_n x[b,c,n]*w[b,n])
//   M[b,c,m]    = sum_n x[b,c,n]*x[b,m,n]*rnorm[b,n]        (GEMM1, NT)
//   out[b,c,n]  = x + gamma*tailor[c]*(colsum[n] + rnorm[n]*sum_m M[c,m]*x[m,n])  (GEMM2)

#define BB 16
#define CC 512
#define NN 4096
#define EPSF 1e-6f

// Scratch (allocation-free rule: __device__ globals)
__device__ float g_rnorm[BB * NN];
__device__ float g_colsum[BB * NN];
__device__ float g_w[BB * NN];
__device__ float g_tailor[BB * CC];
__device__ float g_M[BB * CC * CC];   // 16 MB

// ---------------------------------------------------------------------------
// Kernel 1: per-column stats over channel dim. Threads = consecutive n ->
// every load is fully coalesced; loop over c is the strided dim.
// ---------------------------------------------------------------------------
__global__ void col_stats_kernel(const float* __restrict__ x) {
    int idx = blockIdx.x * blockDim.x + threadIdx.x;   // over B*N
    int b = idx >> 12;            // / 4096
    const float* p = x + (size_t)b * CC * NN + (idx & (NN - 1));
    float ss = 0.f, cs = 0.f;
#pragma unroll 8
    for (int c = 0; c < CC; c++) {
        float v = __ldg(p + (size_t)c * NN);
        ss = fmaf(v, v, ss);
        cs += v;
    }
    float rn = rsqrtf(ss);
    g_rnorm[idx]  = rn;
    g_colsum[idx] = cs;
    g_w[idx]      = rn * fmaf(cs, rn, EPSF);
}

// ---------------------------------------------------------------------------
// Kernel 2: tailor[b,c] = 1/(N + <x[b,c,:], w[b,:]>). One block per (b,c).
// ---------------------------------------------------------------------------
__global__ void tailor_kernel(const float* __restrict__ x) {
    int b = blockIdx.x >> 9;          // / 512
    int c = blockIdx.x & (CC - 1);
    const float* row = x + ((size_t)b * CC + c) * NN;
    const float* w   = g_w + b * NN;

    float s = 0.f;
    for (int n = threadIdx.x; n < NN; n += 256)
        s = fmaf(row[n], w[n], s);

#pragma unroll
    for (int o = 16; o > 0; o >>= 1)
        s += __shfl_down_sync(0xffffffffu, s, o);

    __shared__ float red[8];
    int lane = threadIdx.x & 31, wid = threadIdx.x >> 5;
    if (lane == 0) red[wid] = s;
    __syncthreads();
    if (threadIdx.x < 32) {
        s = (threadIdx.x < 8) ? red[threadIdx.x] : 0.f;
#pragma unroll
        for (int o = 4; o > 0; o >>= 1)
            s += __shfl_down_sync(0xffffffffu, s, o);
        if (threadIdx.x == 0)
            g_tailor[blockIdx.x] = 1.f / ((float)NN + s);
    }
}

// ---------------------------------------------------------------------------
// Kernel 3: GEMM1 (NT, rnorm folded into B side):
//   M[c,m] = sum_n V[c,n] * (V[m,n]*rnorm[n]),  C=512 x C=512, K=N=4096.
// 128x128 tile, BK=16, 256 threads, 8x8 per thread, fp32.
// ---------------------------------------------------------------------------
__global__ void gemm1_kernel(const float* __restrict__ x) {
    const int b  = blockIdx.z;
    const int cb = blockIdx.y * 128;
    const int mb = blockIdx.x * 128;
    const float* V  = x + (size_t)b * CC * NN;
    const float* rn = g_rnorm + b * NN;

    __shared__ __align__(16) float As[16][132];
    __shared__ __align__(16) float Bs[16][132];

    const int tid = threadIdx.x;
    const int tx = tid & 15, ty = tid >> 4;

    float acc[8][8];
#pragma unroll
    for (int i = 0; i < 8; i++)
#pragma unroll
        for (int j = 0; j < 8; j++) acc[i][j] = 0.f;

    for (int k0 = 0; k0 < NN; k0 += 16) {
#pragma unroll
        for (int it = 0; it < 2; it++) {
            int f   = tid + it * 256;
            int row = f >> 2;           // 0..127
            int kq  = (f & 3) << 2;     // 0,4,8,12
            float4 av = *(const float4*)(V + (size_t)(cb + row) * NN + k0 + kq);
            float4 bv = *(const float4*)(V + (size_t)(mb + row) * NN + k0 + kq);
            float4 rv = *(const float4*)(rn + k0 + kq);
            As[kq + 0][row] = av.x; As[kq + 1][row] = av.y;
            As[kq + 2][row] = av.z; As[kq + 3][row] = av.w;
            Bs[kq + 0][row] = bv.x * rv.x; Bs[kq + 1][row] = bv.y * rv.y;
            Bs[kq + 2][row] = bv.z * rv.z; Bs[kq + 3][row] = bv.w * rv.w;
        }
        __syncthreads();
#pragma unroll
        for (int kk = 0; kk < 16; kk++) {
            float a[8], bbv[8];
            *(float4*)&a[0]   = *(const float4*)&As[kk][ty * 8];
            *(float4*)&a[4]   = *(const float4*)&As[kk][ty * 8 + 4];
            *(float4*)&bbv[0] = *(const float4*)&Bs[kk][tx * 8];
            *(float4*)&bbv[4] = *(const float4*)&Bs[kk][tx * 8 + 4];
#pragma unroll
            for (int i = 0; i < 8; i++)
#pragma unroll
                for (int j = 0; j < 8; j++)
                    acc[i][j] = fmaf(a[i], bbv[j], acc[i][j]);
        }
        __syncthreads();
    }

    float* Mout = g_M + (size_t)b * CC * CC;
#pragma unroll
    for (int i = 0; i < 8; i++) {
        int c = cb + ty * 8 + i;
        float* dst = Mout + (size_t)c * CC + mb + tx * 8;
        *(float4*)dst       = make_float4(acc[i][0], acc[i][1], acc[i][2], acc[i][3]);
        *(float4*)(dst + 4) = make_float4(acc[i][4], acc[i][5], acc[i][6], acc[i][7]);
    }
}

// ---------------------------------------------------------------------------
// Kernel 4: GEMM2 + fused epilogue:
//   S[c,n] = sum_m M[c,m] * V[m,n]   (C=512 x N=4096, K=C=512)
//   out    = x + gamma*tailor[c]*(colsum[n] + rnorm[n]*S[c,n])
// ---------------------------------------------------------------------------
__global__ void gemm2_kernel(const float* __restrict__ x,
                             const float* __restrict__ gptr,
                             float* __restrict__ out) {
    const int b  = blockIdx.z;
    const int cb = blockIdx.y * 128;
    const int nb = blockIdx.x * 128;
    const float* A = g_M + (size_t)b * CC * CC;
    const float* V = x + (size_t)b * CC * NN;

    __shared__ __align__(16) float As[16][132];
    __shared__ __align__(16) float Bs[16][132];

    const int tid = threadIdx.x;
    const int tx = tid & 15, ty = tid >> 4;

    float acc[8][8];
#pragma unroll
    for (int i = 0; i < 8; i++)
#pragma unroll
        for (int j = 0; j < 8; j++) acc[i][j] = 0.f;

    for (int k0 = 0; k0 < CC; k0 += 16) {
#pragma unroll
        for (int it = 0; it < 2; it++) {
            int f = tid + it * 256;
            // A tile: 128 rows (c) x 16 (k=m), transpose into As[k][c]
            int arow = f >> 2;
            int akq  = (f & 3) << 2;
            float4 av = *(const float4*)(A + (size_t)(cb + arow) * CC + k0 + akq);
            As[akq + 0][arow] = av.x; As[akq + 1][arow] = av.y;
            As[akq + 2][arow] = av.z; As[akq + 3][arow] = av.w;
            // B tile: 16 rows (k=m) x 128 (n), already k-major -> direct copy
            int brow = f >> 5;            // 0..15
            int bc4  = (f & 31) << 2;     // 0..124
            *(float4*)&Bs[brow][bc4] =
                *(const float4*)(V + (size_t)(k0 + brow) * NN + nb + bc4);
        }
        __syncthreads();
#pragma unroll
        for (int kk = 0; kk < 16; kk++) {
            float a[8], bbv[8];
            *(float4*)&a[0]   = *(const float4*)&As[kk][ty * 8];
            *(float4*)&a[4]   = *(const float4*)&As[kk][ty * 8 + 4];
            *(float4*)&bbv[0] = *(const float4*)&Bs[kk][tx * 8];
            *(float4*)&bbv[4] = *(const float4*)&Bs[kk][tx * 8 + 4];
#pragma unroll
            for (int i = 0; i < 8; i++)
#pragma unroll
                for (int j = 0; j < 8; j++)
                    acc[i][j] = fmaf(a[i], bbv[j], acc[i][j]);
        }
        __syncthreads();
    }

    // Epilogue
    float gamma = __ldg(gptr);
    float cs[8], rnv[8];
    {
        const float* csP = g_colsum + b * NN + nb + tx * 8;
        const float* rnP = g_rnorm  + b * NN + nb + tx * 8;
        *(float4*)&cs[0]  = *(const float4*)csP;
        *(float4*)&cs[4]  = *(const float4*)(csP + 4);
        *(float4*)&rnv[0] = *(const float4*)rnP;
        *(float4*)&rnv[4] = *(const float4*)(rnP + 4);
    }
#pragma unroll
    for (int i = 0; i < 8; i++) {
        int c = cb + ty * 8 + i;
        float tg = g_tailor[b * CC + c] * gamma;
        const float* xp = x   + ((size_t)b * CC + c) * NN + nb + tx * 8;
        float*       op = out + ((size_t)b * CC + c) * NN + nb + tx * 8;
        float4 x0 = *(const float4*)xp;
        float4 x1 = *(const float4*)(xp + 4);
        float4 r0, r1;
        r0.x = fmaf(tg, fmaf(rnv[0], acc[i][0], cs[0]), x0.x);
        r0.y = fmaf(tg, fmaf(rnv[1], acc[i][1], cs[1]), x0.y);
        r0.z = fmaf(tg, fmaf(rnv[2], acc[i][2], cs[2]), x0.z);
        r0.w = fmaf(tg, fmaf(rnv[3], acc[i][3], cs[3]), x0.w);
        r1.x = fmaf(tg, fmaf(rnv[4], acc[i][4], cs[4]), x1.x);
        r1.y = fmaf(tg, fmaf(rnv[5], acc[i][5], cs[5]), x1.y);
        r1.z = fmaf(tg, fmaf(rnv[6], acc[i][6], cs[6]), x1.z);
        r1.w = fmaf(tg, fmaf(rnv[7], acc[i][7], cs[7]), x1.w);
        *(float4*)op       = r0;
        *(float4*)(op + 4) = r1;
    }
}

// ---------------------------------------------------------------------------
extern "C" void kernel_launch(void* const* d_in, const int* in_sizes, int n_in,
                              void* d_out, int out_size) {
    const float* x     = (const float*)d_in[0];
    const float* gamma = (const float*)d_in[1];
    float* out = (float*)d_out;

    col_stats_kernel<<<(BB * NN) / 256, 256>>>(x);
    tailor_kernel<<<BB * CC, 256>>>(x);
    gemm1_kernel<<<dim3(CC / 128, CC / 128, BB), 256>>>(x);
    gemm2_kernel<<<dim3(NN / 128, CC / 128, BB), 256>>>(x, gamma, out);
}

// round 10
// speedup vs baseline: 2.5036x; 2.5036x over previous
#include <cuda_runtime.h>
#include <cuda_bf16.h>
#include <cstdint>

#define BB 16
#define CC 512
#define NN 4096
#define EPSF 1e-6f

// ---------------- device scratch (allocation-free rule) ----------------
__device__ float g_rnorm [BB * NN];
__device__ float g_colsum[BB * NN];
__device__ float g_w     [BB * NN];
__device__ float g_tailor[BB * CC];
__device__ __nv_bfloat16 g_xb [(size_t)BB * CC * NN];   // bf16(x)        [b,c,n]
__device__ __nv_bfloat16 g_xnb[(size_t)BB * CC * NN];   // bf16(x*rnorm)  [b,c,n]
__device__ __nv_bfloat16 g_xbT[(size_t)BB * NN * CC];   // bf16(x) transp [b,n,c]
__device__ __nv_bfloat16 g_Mb [(size_t)BB * CC * CC];   // bf16(M)        [b,c,m]

// ---------------- helpers ----------------
__device__ __forceinline__ uint32_t smem_u32(const void* p) {
    uint32_t a;
    asm("{ .reg .u64 t; cvta.to.shared.u64 t, %1; cvt.u32.u64 %0, t; }" : "=r"(a) : "l"(p));
    return a;
}
__device__ __forceinline__ uint32_t pack_bf16x2(float lo, float hi) {
    uint32_t r;
    asm("cvt.rn.bf16x2.f32 %0, %1, %2;" : "=r"(r) : "f"(hi), "f"(lo));
    return r;
}
__device__ __forceinline__ void ldsm_x4(uint32_t& r0, uint32_t& r1, uint32_t& r2,
                                        uint32_t& r3, uint32_t addr) {
    asm volatile("ldmatrix.sync.aligned.m8n8.x4.shared.b16 {%0,%1,%2,%3}, [%4];"
                 : "=r"(r0), "=r"(r1), "=r"(r2), "=r"(r3) : "r"(addr));
}
__device__ __forceinline__ void mma16816(float* c, const uint32_t* a,
                                         uint32_t b0, uint32_t b1) {
    asm volatile(
        "mma.sync.aligned.m16n8k16.row.col.f32.bf16.bf16.f32 "
        "{%0,%1,%2,%3}, {%4,%5,%6,%7}, {%8,%9}, {%0,%1,%2,%3};"
        : "+f"(c[0]), "+f"(c[1]), "+f"(c[2]), "+f"(c[3])
        : "r"(a[0]), "r"(a[1]), "r"(a[2]), "r"(a[3]), "r"(b0), "r"(b1));
}

#define STRIDE 40   // bf16 elems per smem row (32 data + 8 pad) -> 80B rows

// ===========================================================================
// Kernel 1: per-column stats over channel dim
// ===========================================================================
__global__ void col_stats_kernel(const float* __restrict__ x) {
    int idx = blockIdx.x * blockDim.x + threadIdx.x;   // B*N
    int b = idx >> 12;
    const float* p = x + (size_t)b * CC * NN + (idx & (NN - 1));
    float ss = 0.f, cs = 0.f;
#pragma unroll 8
    for (int c = 0; c < CC; c++) {
        float v = __ldg(p + (size_t)c * NN);
        ss = fmaf(v, v, ss);
        cs += v;
    }
    float rn = rsqrtf(ss);
    g_rnorm[idx]  = rn;
    g_colsum[idx] = cs;
    g_w[idx]      = rn * fmaf(cs, rn, EPSF);
}

// ===========================================================================
// Kernel 2: tailor[b,c] = 1/(N + <x[b,c,:], w[b,:]>)
// ===========================================================================
__global__ void tailor_kernel(const float* __restrict__ x) {
    int b = blockIdx.x >> 9;
    const float* row = x + (size_t)blockIdx.x * NN;
    const float* w   = g_w + b * NN;
    float s = 0.f;
    for (int n = threadIdx.x; n < NN; n += 256)
        s = fmaf(row[n], w[n], s);
#pragma unroll
    for (int o = 16; o > 0; o >>= 1) s += __shfl_down_sync(0xffffffffu, s, o);
    __shared__ float red[8];
    int lane = threadIdx.x & 31, wid = threadIdx.x >> 5;
    if (lane == 0) red[wid] = s;
    __syncthreads();
    if (threadIdx.x < 32) {
        s = (threadIdx.x < 8) ? red[threadIdx.x] : 0.f;
#pragma unroll
        for (int o = 4; o > 0; o >>= 1) s += __shfl_down_sync(0xffffffffu, s, o);
        if (threadIdx.x == 0) g_tailor[blockIdx.x] = 1.f / ((float)NN + s);
    }
}

// ===========================================================================
// Kernel 3: bf16 conversions (xb, xnb) + transpose (xbT). 64x64 tiles.
// ===========================================================================
__global__ void convert_kernel(const float* __restrict__ x) {
    __shared__ float S[64][65];
    int b = blockIdx.z, c0 = blockIdx.y * 64, n0 = blockIdx.x * 64;
    int t = threadIdx.x;
    const float* rn = g_rnorm + b * NN + n0;
#pragma unroll
    for (int i = 0; i < 4; i++) {
        int idx = t + i * 256;
        int row = idx >> 4, v = idx & 15;
        size_t go = ((size_t)(b * CC + c0 + row)) * NN + n0 + v * 4;
        float4 xv = *(const float4*)(x + go);
        float4 rv = *(const float4*)(rn + v * 4);
        S[row][v * 4 + 0] = xv.x; S[row][v * 4 + 1] = xv.y;
        S[row][v * 4 + 2] = xv.z; S[row][v * 4 + 3] = xv.w;
        uint2 pb, pn;
        pb.x = pack_bf16x2(xv.x, xv.y);
        pb.y = pack_bf16x2(xv.z, xv.w);
        pn.x = pack_bf16x2(xv.x * rv.x, xv.y * rv.y);
        pn.y = pack_bf16x2(xv.z * rv.z, xv.w * rv.w);
        *(uint2*)(g_xb  + go) = pb;
        *(uint2*)(g_xnb + go) = pn;
    }
    __syncthreads();
#pragma unroll
    for (int i = 0; i < 8; i++) {
        int idx = t + i * 256;
        int nl = idx >> 5, c2 = (idx & 31) * 2;
        uint32_t p = pack_bf16x2(S[c2][nl], S[c2 + 1][nl]);
        *(uint32_t*)(g_xbT + ((size_t)b * NN + n0 + nl) * CC + c0 + c2) = p;
    }
}

// ===========================================================================
// GEMM building blocks (128x128 block, BK=32, 8 warps 4x2, warp tile 32x64)
// ===========================================================================
__device__ __forceinline__ void ldg_stage(const __nv_bfloat16* __restrict__ A,
                                          const __nv_bfloat16* __restrict__ Bp,
                                          int lda, int ldb, int k0, int tid,
                                          uint4* ra, uint4* rb) {
#pragma unroll
    for (int i = 0; i < 2; i++) {
        int f = tid + i * 256;
        int row = f >> 2, kc = f & 3;
        ra[i] = *(const uint4*)(A  + (size_t)row * lda + k0 + kc * 8);
        rb[i] = *(const uint4*)(Bp + (size_t)row * ldb + k0 + kc * 8);
    }
}
__device__ __forceinline__ void sts_stage(__nv_bfloat16* sA, __nv_bfloat16* sB,
                                          int tid, const uint4* ra, const uint4* rb) {
#pragma unroll
    for (int i = 0; i < 2; i++) {
        int f = tid + i * 256;
        int row = f >> 2, kc = f & 3;
        *(uint4*)(sA + row * STRIDE + kc * 8) = ra[i];
        *(uint4*)(sB + row * STRIDE + kc * 8) = rb[i];
    }
}
__device__ __forceinline__ void compute_tile(uint32_t sa, uint32_t sb,
                                             int wm, int wn, int lane,
                                             float acc[2][8][4]) {
    const uint32_t lrow = (lane & 15), lchunk = (lane >> 4) << 4;
#pragma unroll
    for (int ks = 0; ks < 2; ks++) {
        uint32_t a[2][4];
#pragma unroll
        for (int mt = 0; mt < 2; mt++)
            ldsm_x4(a[mt][0], a[mt][1], a[mt][2], a[mt][3],
                    sa + (wm * 32 + mt * 16 + lrow) * 80 + ks * 32 + lchunk);
        uint32_t bf[4][4];
#pragma unroll
        for (int p = 0; p < 4; p++)
            ldsm_x4(bf[p][0], bf[p][1], bf[p][2], bf[p][3],
                    sb + (wn * 64 + p * 16 + lrow) * 80 + ks * 32 + lchunk);
#pragma unroll
        for (int mt = 0; mt < 2; mt++)
#pragma unroll
            for (int nt = 0; nt < 8; nt++)
                mma16816(acc[mt][nt], a[mt],
                         bf[nt >> 1][nt & 1], bf[nt >> 1][(nt & 1) + 2]);
    }
}

// ===========================================================================
// Kernel 4: GEMM1  Mb[c,m] = sum_n xb[c,n] * xnb[m,n]   (K = 4096)
// ===========================================================================
__global__ void __launch_bounds__(256, 2) gemm1_mma() {
    __shared__ __align__(16) __nv_bfloat16 sA[2][128 * STRIDE];
    __shared__ __align__(16) __nv_bfloat16 sB[2][128 * STRIDE];
    const int tid = threadIdx.x, lane = tid & 31, warp = tid >> 5;
    const int wm = warp & 3, wn = warp >> 2;
    const int b = blockIdx.z, cb = blockIdx.y * 128, mb = blockIdx.x * 128;
    const __nv_bfloat16* A  = g_xb  + (size_t)(b * CC + cb) * NN;
    const __nv_bfloat16* Bp = g_xnb + (size_t)(b * CC + mb) * NN;

    float acc[2][8][4];
#pragma unroll
    for (int i = 0; i < 2; i++)
#pragma unroll
        for (int j = 0; j < 8; j++)
#pragma unroll
            for (int q = 0; q < 4; q++) acc[i][j][q] = 0.f;

    uint4 ra[2], rb[2];
    ldg_stage(A, Bp, NN, NN, 0, tid, ra, rb);
    sts_stage(sA[0], sB[0], tid, ra, rb);
    __syncthreads();

    const int KT = NN / 32;
    for (int kt = 0; kt < KT; kt++) {
        if (kt + 1 < KT) ldg_stage(A, Bp, NN, NN, (kt + 1) * 32, tid, ra, rb);
        compute_tile(smem_u32(sA[kt & 1]), smem_u32(sB[kt & 1]), wm, wn, lane, acc);
        if (kt + 1 < KT) sts_stage(sA[(kt + 1) & 1], sB[(kt + 1) & 1], tid, ra, rb);
        __syncthreads();
    }

    __nv_bfloat16* Mo = g_Mb + (size_t)b * CC * CC;
#pragma unroll
    for (int mt = 0; mt < 2; mt++) {
        int r0 = cb + wm * 32 + mt * 16 + (lane >> 2);
#pragma unroll
        for (int nt = 0; nt < 8; nt++) {
            int col = mb + wn * 64 + nt * 8 + 2 * (lane & 3);
            *(uint32_t*)(Mo + (size_t)r0 * CC + col) =
                pack_bf16x2(acc[mt][nt][0], acc[mt][nt][1]);
            *(uint32_t*)(Mo + (size_t)(r0 + 8) * CC + col) =
                pack_bf16x2(acc[mt][nt][2], acc[mt][nt][3]);
        }
    }
}

// ===========================================================================
// Kernel 5: GEMM2  S[c,n] = sum_m Mb[c,m]*xbT[n,m]; fused epilogue:
//   out = x + gamma*tailor[c]*(colsum[n] + rnorm[n]*S[c,n])
// ===========================================================================
__global__ void __launch_bounds__(256, 2) gemm2_mma(const float* __restrict__ x,
                                                    const float* __restrict__ gptr,
                                                    float* __restrict__ out) {
    __shared__ __align__(16) __nv_bfloat16 sA[2][128 * STRIDE];
    __shared__ __align__(16) __nv_bfloat16 sB[2][128 * STRIDE];
    const int tid = threadIdx.x, lane = tid & 31, warp = tid >> 5;
    const int wm = warp & 3, wn = warp >> 2;
    const int b = blockIdx.z, cb = blockIdx.y * 128, nb = blockIdx.x * 128;
    const __nv_bfloat16* A  = g_Mb  + (size_t)(b * CC + cb) * CC;
    const __nv_bfloat16* Bp = g_xbT + ((size_t)b * NN + nb) * CC;

    float acc[2][8][4];
#pragma unroll
    for (int i = 0; i < 2; i++)
#pragma unroll
        for (int j = 0; j < 8; j++)
#pragma unroll
            for (int q = 0; q < 4; q++) acc[i][j][q] = 0.f;

    uint4 ra[2], rb[2];
    ldg_stage(A, Bp, CC, CC, 0, tid, ra, rb);
    sts_stage(sA[0], sB[0], tid, ra, rb);
    __syncthreads();

    const int KT = CC / 32;
    for (int kt = 0; kt < KT; kt++) {
        if (kt + 1 < KT) ldg_stage(A, Bp, CC, CC, (kt + 1) * 32, tid, ra, rb);
        compute_tile(smem_u32(sA[kt & 1]), smem_u32(sB[kt & 1]), wm, wn, lane, acc);
        if (kt + 1 < KT) sts_stage(sA[(kt + 1) & 1], sB[(kt + 1) & 1], tid, ra, rb);
        __syncthreads();
    }

    float gamma = __ldg(gptr);
#pragma unroll
    for (int mt = 0; mt < 2; mt++) {
        int c0 = cb + wm * 32 + mt * 16 + (lane >> 2);
#pragma unroll
        for (int half = 0; half < 2; half++) {
            int c = c0 + half * 8;
            float tg = gamma * g_tailor[b * CC + c];
            const float* xrow = x   + ((size_t)b * CC + c) * NN;
            float*       orow = out + ((size_t)b * CC + c) * NN;
#pragma unroll
            for (int nt = 0; nt < 8; nt++) {
                int n = nb + wn * 64 + nt * 8 + 2 * (lane & 3);
                float Sx = acc[mt][nt][half * 2];
                float Sy = acc[mt][nt][half * 2 + 1];
                float2 cs = *(const float2*)(g_colsum + b * NN + n);
                float2 rn = *(const float2*)(g_rnorm  + b * NN + n);
                float2 xv = *(const float2*)(xrow + n);
                float2 o;
                o.x = fmaf(tg, fmaf(rn.x, Sx, cs.x), xv.x);
                o.y = fmaf(tg, fmaf(rn.y, Sy, cs.y), xv.y);
                *(float2*)(orow + n) = o;
            }
        }
    }
}

// ===========================================================================
extern "C" void kernel_launch(void* const* d_in, const int* in_sizes, int n_in,
                              void* d_out, int out_size) {
    const float* x     = (const float*)d_in[0];
    const float* gamma = (const float*)d_in[1];
    float* out = (float*)d_out;

    col_stats_kernel<<<(BB * NN) / 256, 256>>>(x);
    convert_kernel<<<dim3(NN / 64, CC / 64, BB), 256>>>(x);
    tailor_kernel<<<BB * CC, 256>>>(x);
    gemm1_mma<<<dim3(CC / 128, CC / 128, BB), 256>>>();
    gemm2_mma<<<dim3(NN / 128, CC / 128, BB), 256>>>(x, gamma, out);
}

// round 11
// speedup vs baseline: 3.4284x; 1.3694x over previous
#include <cuda_runtime.h>
#include <cuda_bf16.h>
#include <cstdint>

#define BB 16
#define CC 512
#define NN 4096
#define EPSF 1e-6f

// ---------------- device scratch (allocation-free rule) ----------------
__device__ float g_rnorm [BB * NN];
__device__ float g_colsum[BB * NN];
__device__ float g_w     [BB * NN];
__device__ float g_tailor[BB * CC];
__device__ __nv_bfloat16 g_xb [(size_t)BB * CC * NN];   // bf16(x)        [b,c,n]
__device__ __nv_bfloat16 g_xnb[(size_t)BB * CC * NN];   // bf16(x*rnorm)  [b,c,n]
__device__ __nv_bfloat16 g_xbT[(size_t)BB * NN * CC];   // bf16(x) transp [b,n,c]
__device__ __nv_bfloat16 g_Mb [(size_t)BB * CC * CC];   // bf16(M)        [b,c,m]

// ---------------- helpers ----------------
__device__ __forceinline__ uint32_t smem_u32(const void* p) {
    uint32_t a;
    asm("{ .reg .u64 t; cvta.to.shared.u64 t, %1; cvt.u32.u64 %0, t; }" : "=r"(a) : "l"(p));
    return a;
}
__device__ __forceinline__ uint32_t pack_bf16x2(float lo, float hi) {
    uint32_t r;
    asm("cvt.rn.bf16x2.f32 %0, %1, %2;" : "=r"(r) : "f"(hi), "f"(lo));
    return r;
}
__device__ __forceinline__ void ldsm_x4(uint32_t& r0, uint32_t& r1, uint32_t& r2,
                                        uint32_t& r3, uint32_t addr) {
    asm volatile("ldmatrix.sync.aligned.m8n8.x4.shared.b16 {%0,%1,%2,%3}, [%4];"
                 : "=r"(r0), "=r"(r1), "=r"(r2), "=r"(r3) : "r"(addr));
}
__device__ __forceinline__ void mma16816(float* c, const uint32_t* a,
                                         uint32_t b0, uint32_t b1) {
    asm volatile(
        "mma.sync.aligned.m16n8k16.row.col.f32.bf16.bf16.f32 "
        "{%0,%1,%2,%3}, {%4,%5,%6,%7}, {%8,%9}, {%0,%1,%2,%3};"
        : "+f"(c[0]), "+f"(c[1]), "+f"(c[2]), "+f"(c[3])
        : "r"(a[0]), "r"(a[1]), "r"(a[2]), "r"(a[3]), "r"(b0), "r"(b1));
}

#define STRIDE 40   // bf16 elems per smem row (32 data + 8 pad) -> 80B rows

// ===========================================================================
// Kernel 1: per-column stats over channel dim
// ===========================================================================
__global__ void col_stats_kernel(const float* __restrict__ x) {
    int idx = blockIdx.x * blockDim.x + threadIdx.x;   // B*N
    int b = idx >> 12;
    const float* p = x + (size_t)b * CC * NN + (idx & (NN - 1));
    float ss = 0.f, cs = 0.f;
#pragma unroll 8
    for (int c = 0; c < CC; c++) {
        float v = __ldg(p + (size_t)c * NN);
        ss = fmaf(v, v, ss);
        cs += v;
    }
    float rn = rsqrtf(ss);
    g_rnorm[idx]  = rn;
    g_colsum[idx] = cs;
    g_w[idx]      = rn * fmaf(cs, rn, EPSF);
}

// ===========================================================================
// Kernel 2: tailor[b,c] = 1/(N + <x[b,c,:], w[b,:]>)
// ===========================================================================
__global__ void tailor_kernel(const float* __restrict__ x) {
    int b = blockIdx.x >> 9;
    const float* row = x + (size_t)blockIdx.x * NN;
    const float* w   = g_w + b * NN;
    float s = 0.f;
    for (int n = threadIdx.x; n < NN; n += 256)
        s = fmaf(row[n], w[n], s);
#pragma unroll
    for (int o = 16; o > 0; o >>= 1) s += __shfl_down_sync(0xffffffffu, s, o);
    __shared__ float red[8];
    int lane = threadIdx.x & 31, wid = threadIdx.x >> 5;
    if (lane == 0) red[wid] = s;
    __syncthreads();
    if (threadIdx.x < 32) {
        s = (threadIdx.x < 8) ? red[threadIdx.x] : 0.f;
#pragma unroll
        for (int o = 4; o > 0; o >>= 1) s += __shfl_down_sync(0xffffffffu, s, o);
        if (threadIdx.x == 0) g_tailor[blockIdx.x] = 1.f / ((float)NN + s);
    }
}

// ===========================================================================
// Kernel 3: bf16 conversions (xb, xnb) + transpose (xbT). 64x64 tiles.
// ===========================================================================
__global__ void convert_kernel(const float* __restrict__ x) {
    __shared__ float S[64][65];
    int b = blockIdx.z, c0 = blockIdx.y * 64, n0 = blockIdx.x * 64;
    int t = threadIdx.x;
    const float* rn = g_rnorm + b * NN + n0;
#pragma unroll
    for (int i = 0; i < 4; i++) {
        int idx = t + i * 256;
        int row = idx >> 4, v = idx & 15;
        size_t go = ((size_t)(b * CC + c0 + row)) * NN + n0 + v * 4;
        float4 xv = *(const float4*)(x + go);
        float4 rv = *(const float4*)(rn + v * 4);
        S[row][v * 4 + 0] = xv.x; S[row][v * 4 + 1] = xv.y;
        S[row][v * 4 + 2] = xv.z; S[row][v * 4 + 3] = xv.w;
        uint2 pb, pn;
        pb.x = pack_bf16x2(xv.x, xv.y);
        pb.y = pack_bf16x2(xv.z, xv.w);
        pn.x = pack_bf16x2(xv.x * rv.x, xv.y * rv.y);
        pn.y = pack_bf16x2(xv.z * rv.z, xv.w * rv.w);
        *(uint2*)(g_xb  + go) = pb;
        *(uint2*)(g_xnb + go) = pn;
    }
    __syncthreads();
#pragma unroll
    for (int i = 0; i < 8; i++) {
        int idx = t + i * 256;
        int nl = idx >> 5, c2 = (idx & 31) * 2;
        uint32_t p = pack_bf16x2(S[c2][nl], S[c2 + 1][nl]);
        *(uint32_t*)(g_xbT + ((size_t)b * NN + n0 + nl) * CC + c0 + c2) = p;
    }
}

// ===========================================================================
// GEMM building blocks (128x128 block, BK=32, 8 warps 4x2, warp tile 32x64)
// ===========================================================================
__device__ __forceinline__ void ldg_stage(const __nv_bfloat16* __restrict__ A,
                                          const __nv_bfloat16* __restrict__ Bp,
                                          int lda, int ldb, int k0, int tid,
                                          uint4* ra, uint4* rb) {
#pragma unroll
    for (int i = 0; i < 2; i++) {
        int f = tid + i * 256;
        int row = f >> 2, kc = f & 3;
        ra[i] = *(const uint4*)(A  + (size_t)row * lda + k0 + kc * 8);
        rb[i] = *(const uint4*)(Bp + (size_t)row * ldb + k0 + kc * 8);
    }
}
__device__ __forceinline__ void sts_stage(__nv_bfloat16* sA, __nv_bfloat16* sB,
                                          int tid, const uint4* ra, const uint4* rb) {
#pragma unroll
    for (int i = 0; i < 2; i++) {
        int f = tid + i * 256;
        int row = f >> 2, kc = f & 3;
        *(uint4*)(sA + row * STRIDE + kc * 8) = ra[i];
        *(uint4*)(sB + row * STRIDE + kc * 8) = rb[i];
    }
}
__device__ __forceinline__ void compute_tile(uint32_t sa, uint32_t sb,
                                             int wm, int wn, int lane,
                                             float acc[2][8][4]) {
    const uint32_t lrow = (lane & 15), lchunk = (lane >> 4) << 4;
#pragma unroll
    for (int ks = 0; ks < 2; ks++) {
        uint32_t a[2][4];
#pragma unroll
        for (int mt = 0; mt < 2; mt++)
            ldsm_x4(a[mt][0], a[mt][1], a[mt][2], a[mt][3],
                    sa + (wm * 32 + mt * 16 + lrow) * 80 + ks * 32 + lchunk);
        uint32_t bf[4][4];
#pragma unroll
        for (int p = 0; p < 4; p++)
            ldsm_x4(bf[p][0], bf[p][1], bf[p][2], bf[p][3],
                    sb + (wn * 64 + p * 16 + lrow) * 80 + ks * 32 + lchunk);
#pragma unroll
        for (int mt = 0; mt < 2; mt++)
#pragma unroll
            for (int nt = 0; nt < 8; nt++)
                mma16816(acc[mt][nt], a[mt],
                         bf[nt >> 1][nt & 1], bf[nt >> 1][(nt & 1) + 2]);
    }
}

// ===========================================================================
// Kernel 4: GEMM1  Mb[c,m] = sum_n xb[c,n] * xnb[m,n]   (K = 4096)
// ===========================================================================
__global__ void __launch_bounds__(256, 2) gemm1_mma() {
    __shared__ __align__(16) __nv_bfloat16 sA[2][128 * STRIDE];
    __shared__ __align__(16) __nv_bfloat16 sB[2][128 * STRIDE];
    const int tid = threadIdx.x, lane = tid & 31, warp = tid >> 5;
    const int wm = warp & 3, wn = warp >> 2;
    const int b = blockIdx.z, cb = blockIdx.y * 128, mb = blockIdx.x * 128;
    const __nv_bfloat16* A  = g_xb  + (size_t)(b * CC + cb) * NN;
    const __nv_bfloat16* Bp = g_xnb + (size_t)(b * CC + mb) * NN;

    float acc[2][8][4];
#pragma unroll
    for (int i = 0; i < 2; i++)
#pragma unroll
        for (int j = 0; j < 8; j++)
#pragma unroll
            for (int q = 0; q < 4; q++) acc[i][j][q] = 0.f;

    uint4 ra[2], rb[2];
    ldg_stage(A, Bp, NN, NN, 0, tid, ra, rb);
    sts_stage(sA[0], sB[0], tid, ra, rb);
    __syncthreads();

    const int KT = NN / 32;
    for (int kt = 0; kt < KT; kt++) {
        if (kt + 1 < KT) ldg_stage(A, Bp, NN, NN, (kt + 1) * 32, tid, ra, rb);
        compute_tile(smem_u32(sA[kt & 1]), smem_u32(sB[kt & 1]), wm, wn, lane, acc);
        if (kt + 1 < KT) sts_stage(sA[(kt + 1) & 1], sB[(kt + 1) & 1], tid, ra, rb);
        __syncthreads();
    }

    __nv_bfloat16* Mo = g_Mb + (size_t)b * CC * CC;
#pragma unroll
    for (int mt = 0; mt < 2; mt++) {
        int r0 = cb + wm * 32 + mt * 16 + (lane >> 2);
#pragma unroll
        for (int nt = 0; nt < 8; nt++) {
            int col = mb + wn * 64 + nt * 8 + 2 * (lane & 3);
            *(uint32_t*)(Mo + (size_t)r0 * CC + col) =
                pack_bf16x2(acc[mt][nt][0], acc[mt][nt][1]);
            *(uint32_t*)(Mo + (size_t)(r0 + 8) * CC + col) =
                pack_bf16x2(acc[mt][nt][2], acc[mt][nt][3]);
        }
    }
}

// ===========================================================================
// Kernel 5: GEMM2  S[c,n] = sum_m Mb[c,m]*xbT[n,m]; fused epilogue:
//   out = x + gamma*tailor[c]*(colsum[n] + rnorm[n]*S[c,n])
// ===========================================================================
__global__ void __launch_bounds__(256, 2) gemm2_mma(const float* __restrict__ x,
                                                    const float* __restrict__ gptr,
                                                    float* __restrict__ out) {
    __shared__ __align__(16) __nv_bfloat16 sA[2][128 * STRIDE];
    __shared__ __align__(16) __nv_bfloat16 sB[2][128 * STRIDE];
    const int tid = threadIdx.x, lane = tid & 31, warp = tid >> 5;
    const int wm = warp & 3, wn = warp >> 2;
    const int b = blockIdx.z, cb = blockIdx.y * 128, nb = blockIdx.x * 128;
    const __nv_bfloat16* A  = g_Mb  + (size_t)(b * CC + cb) * CC;
    const __nv_bfloat16* Bp = g_xbT + ((size_t)b * NN + nb) * CC;

    float acc[2][8][4];
#pragma unroll
    for (int i = 0; i < 2; i++)
#pragma unroll
        for (int j = 0; j < 8; j++)
#pragma unroll
            for (int q = 0; q < 4; q++) acc[i][j][q] = 0.f;

    uint4 ra[2], rb[2];
    ldg_stage(A, Bp, CC, CC, 0, tid, ra, rb);
    sts_stage(sA[0], sB[0], tid, ra, rb);
    __syncthreads();

    const int KT = CC / 32;
    for (int kt = 0; kt < KT; kt++) {
        if (kt + 1 < KT) ldg_stage(A, Bp, CC, CC, (kt + 1) * 32, tid, ra, rb);
        compute_tile(smem_u32(sA[kt & 1]), smem_u32(sB[kt & 1]), wm, wn, lane, acc);
        if (kt + 1 < KT) sts_stage(sA[(kt + 1) & 1], sB[(kt + 1) & 1], tid, ra, rb);
        __syncthreads();
    }

    float gamma = __ldg(gptr);
#pragma unroll
    for (int mt = 0; mt < 2; mt++) {
        int c0 = cb + wm * 32 + mt * 16 + (lane >> 2);
#pragma unroll
        for (int half = 0; half < 2; half++) {
            int c = c0 + half * 8;
            float tg = gamma * g_tailor[b * CC + c];
            const float* xrow = x   + ((size_t)b * CC + c) * NN;
            float*       orow = out + ((size_t)b * CC + c) * NN;
#pragma unroll
            for (int nt = 0; nt < 8; nt++) {
                int n = nb + wn * 64 + nt * 8 + 2 * (lane & 3);
                float Sx = acc[mt][nt][half * 2];
                float Sy = acc[mt][nt][half * 2 + 1];
                float2 cs = *(const float2*)(g_colsum + b * NN + n);
                float2 rn = *(const float2*)(g_rnorm  + b * NN + n);
                float2 xv = *(const float2*)(xrow + n);
                float2 o;
                o.x = fmaf(tg, fmaf(rn.x, Sx, cs.x), xv.x);
                o.y = fmaf(tg, fmaf(rn.y, Sy, cs.y), xv.y);
                *(float2*)(orow + n) = o;
            }
        }
    }
}

// ===========================================================================
extern "C" void kernel_launch(void* const* d_in, const int* in_sizes, int n_in,
                              void* d_out, int out_size) {
    const float* x     = (const float*)d_in[0];
    const float* gamma = (const float*)d_in[1];
    float* out = (float*)d_out;

    col_stats_kernel<<<(BB * NN) / 256, 256>>>(x);
    convert_kernel<<<dim3(NN / 64, CC / 64, BB), 256>>>(x);
    tailor_kernel<<<BB * CC, 256>>>(x);
    gemm1_mma<<<dim3(CC / 128, CC / 128, BB), 256>>>();
    gemm2_mma<<<dim3(NN / 128, CC / 128, BB), 256>>>(x, gamma, out);
}

// round 12
// speedup vs baseline: 3.7396x; 1.0908x over previous
#include <cuda_runtime.h>
#include <cuda_bf16.h>
#include <cstdint>

#define BB 16
#define CC 512
#define NN 4096
#define EPSF 1e-6f

// ---------------- device scratch (allocation-free rule) ----------------
__device__ float g_rnorm [BB * NN];
__device__ float g_srn   [BB * NN];      // sqrt(rnorm)
__device__ float g_colsum[BB * NN];
__device__ float g_w     [BB * NN];
__device__ float g_tailor[BB * CC];
__device__ __nv_bfloat16 g_yb [(size_t)BB * CC * NN];   // bf16(x*sqrt(rn)) [b,c,n]
__device__ __nv_bfloat16 g_xbT[(size_t)BB * NN * CC];   // bf16(x) transp   [b,n,c]
__device__ __nv_bfloat16 g_Mb [(size_t)BB * CC * CC];   // bf16(M)          [b,c,m]

// ---------------- helpers ----------------
__device__ __forceinline__ uint32_t smem_u32(const void* p) {
    uint32_t a;
    asm("{ .reg .u64 t; cvta.to.shared.u64 t, %1; cvt.u32.u64 %0, t; }" : "=r"(a) : "l"(p));
    return a;
}
__device__ __forceinline__ uint32_t pack_bf16x2(float lo, float hi) {
    uint32_t r;
    asm("cvt.rn.bf16x2.f32 %0, %1, %2;" : "=r"(r) : "f"(hi), "f"(lo));
    return r;
}
__device__ __forceinline__ void ldsm_x4(uint32_t& r0, uint32_t& r1, uint32_t& r2,
                                        uint32_t& r3, uint32_t addr) {
    asm volatile("ldmatrix.sync.aligned.m8n8.x4.shared.b16 {%0,%1,%2,%3}, [%4];"
                 : "=r"(r0), "=r"(r1), "=r"(r2), "=r"(r3) : "r"(addr));
}
__device__ __forceinline__ void mma16816(float* c, const uint32_t* a,
                                         uint32_t b0, uint32_t b1) {
    asm volatile(
        "mma.sync.aligned.m16n8k16.row.col.f32.bf16.bf16.f32 "
        "{%0,%1,%2,%3}, {%4,%5,%6,%7}, {%8,%9}, {%0,%1,%2,%3};"
        : "+f"(c[0]), "+f"(c[1]), "+f"(c[2]), "+f"(c[3])
        : "r"(a[0]), "r"(a[1]), "r"(a[2]), "r"(a[3]), "r"(b0), "r"(b1));
}
__device__ __forceinline__ void cp16(uint32_t dst, const void* src) {
    asm volatile("cp.async.cg.shared.global [%0], [%1], 16;" :: "r"(dst), "l"(src));
}
#define CP_COMMIT() asm volatile("cp.async.commit_group;" ::: "memory")
#define CP_WAIT1()  asm volatile("cp.async.wait_group 1;"  ::: "memory")

#define STRIDE 40          // bf16 per smem row (32 data + 8 pad) = 80 B
#define STG_A   10240u     // 128 * 40 * 2
#define STG_SZ  20480u     // A + B per stage
#define NSTAGE  3
#define SM_DYN  (NSTAGE * STG_SZ)   // 61440

// ===========================================================================
// Kernel 1: per-column stats over channel dim
// ===========================================================================
__global__ void col_stats_kernel(const float* __restrict__ x) {
    int idx = blockIdx.x * blockDim.x + threadIdx.x;   // B*N
    int b = idx >> 12;
    const float* p = x + (size_t)b * CC * NN + (idx & (NN - 1));
    float ss = 0.f, cs = 0.f;
#pragma unroll 8
    for (int c = 0; c < CC; c++) {
        float v = __ldg(p + (size_t)c * NN);
        ss = fmaf(v, v, ss);
        cs += v;
    }
    float rn = rsqrtf(ss);
    g_rnorm[idx]  = rn;
    g_srn[idx]    = sqrtf(rn);
    g_colsum[idx] = cs;
    g_w[idx]      = rn * fmaf(cs, rn, EPSF);
}

// ===========================================================================
// Kernel 2: tailor[b,c] = 1/(N + <x[b,c,:], w[b,:]>)
// ===========================================================================
__global__ void tailor_kernel(const float* __restrict__ x) {
    int b = blockIdx.x >> 9;
    const float* row = x + (size_t)blockIdx.x * NN;
    const float* w   = g_w + b * NN;
    float s = 0.f;
    for (int n = threadIdx.x; n < NN; n += 256)
        s = fmaf(row[n], w[n], s);
#pragma unroll
    for (int o = 16; o > 0; o >>= 1) s += __shfl_down_sync(0xffffffffu, s, o);
    __shared__ float red[8];
    int lane = threadIdx.x & 31, wid = threadIdx.x >> 5;
    if (lane == 0) red[wid] = s;
    __syncthreads();
    if (threadIdx.x < 32) {
        s = (threadIdx.x < 8) ? red[threadIdx.x] : 0.f;
#pragma unroll
        for (int o = 4; o > 0; o >>= 1) s += __shfl_down_sync(0xffffffffu, s, o);
        if (threadIdx.x == 0) g_tailor[blockIdx.x] = 1.f / ((float)NN + s);
    }
}

// ===========================================================================
// Kernel 3: convert: yb = bf16(x*srn) [c,n]; xbT = bf16(x) [n,c]. 64x64 tiles.
// ===========================================================================
__global__ void convert_kernel(const float* __restrict__ x) {
    __shared__ float S[64][65];
    int b = blockIdx.z, c0 = blockIdx.y * 64, n0 = blockIdx.x * 64;
    int t = threadIdx.x;
    const float* srn = g_srn + b * NN + n0;
#pragma unroll
    for (int i = 0; i < 4; i++) {
        int idx = t + i * 256;
        int row = idx >> 4, v = idx & 15;
        size_t go = ((size_t)(b * CC + c0 + row)) * NN + n0 + v * 4;
        float4 xv = *(const float4*)(x + go);
        float4 sv = *(const float4*)(srn + v * 4);
        S[row][v * 4 + 0] = xv.x; S[row][v * 4 + 1] = xv.y;
        S[row][v * 4 + 2] = xv.z; S[row][v * 4 + 3] = xv.w;
        uint2 py;
        py.x = pack_bf16x2(xv.x * sv.x, xv.y * sv.y);
        py.y = pack_bf16x2(xv.z * sv.z, xv.w * sv.w);
        *(uint2*)(g_yb + go) = py;
    }
    __syncthreads();
#pragma unroll
    for (int i = 0; i < 8; i++) {
        int idx = t + i * 256;
        int nl = idx >> 5, c2 = (idx & 31) * 2;
        uint32_t p = pack_bf16x2(S[c2][nl], S[c2 + 1][nl]);
        *(uint32_t*)(g_xbT + ((size_t)b * NN + n0 + nl) * CC + c0 + c2) = p;
    }
}

// ===========================================================================
// GEMM building blocks: 128x128 tile, BK=32, 8 warps (4x2), warp tile 32x64
// ===========================================================================
__device__ __forceinline__ void issue_stage(uint32_t sbase,
                                            const __nv_bfloat16* __restrict__ A,
                                            const __nv_bfloat16* __restrict__ Bp,
                                            int lda, int ldb, int k0, int tid) {
#pragma unroll
    for (int i = 0; i < 4; i++) {
        int f = tid + i * 256;                 // 0..1023
        int half = f >> 9;                     // 0 = A, 1 = B
        int r = (f >> 2) & 127, ch = f & 3;
        const __nv_bfloat16* src =
            (half ? Bp + (size_t)r * ldb : A + (size_t)r * lda) + k0 + ch * 8;
        cp16(sbase + half * STG_A + r * 80 + ch * 16, src);
    }
}

__device__ __forceinline__ void compute_tile(uint32_t sa, uint32_t sb,
                                             int wm, int wn, int lane,
                                             float acc[2][8][4]) {
    const uint32_t lrow = (lane & 15), lchunk = (lane >> 4) << 4;
#pragma unroll
    for (int ks = 0; ks < 2; ks++) {
        uint32_t a[2][4];
#pragma unroll
        for (int mt = 0; mt < 2; mt++)
            ldsm_x4(a[mt][0], a[mt][1], a[mt][2], a[mt][3],
                    sa + (wm * 32 + mt * 16 + lrow) * 80 + ks * 32 + lchunk);
        uint32_t bf[4][4];
#pragma unroll
        for (int p = 0; p < 4; p++)
            ldsm_x4(bf[p][0], bf[p][1], bf[p][2], bf[p][3],
                    sb + (wn * 64 + p * 16 + lrow) * 80 + ks * 32 + lchunk);
#pragma unroll
        for (int mt = 0; mt < 2; mt++)
#pragma unroll
            for (int nt = 0; nt < 8; nt++)
                mma16816(acc[mt][nt], a[mt],
                         bf[nt >> 1][nt & 1], bf[nt >> 1][(nt & 1) + 2]);
    }
}

// ===========================================================================
// Kernel 4: GEMM1 (symmetric)  M = y.y^T, upper-triangle tiles + mirror.
// ===========================================================================
__global__ void __launch_bounds__(256, 2) gemm1_mma() {
    extern __shared__ __align__(128) char dsm[];
    const uint32_t sb0 = smem_u32(dsm);
    const int tid = threadIdx.x, lane = tid & 31, warp = tid >> 5;
    const int wm = warp & 3, wn = warp >> 2;
    const int TI[10] = {0,0,0,0,1,1,1,2,2,3};
    const int TJ[10] = {0,1,2,3,1,2,3,2,3,3};
    const int b = blockIdx.z, ii = TI[blockIdx.x], jj = TJ[blockIdx.x];
    const int cb = ii * 128, mb = jj * 128;
    const __nv_bfloat16* A  = g_yb + (size_t)(b * CC + cb) * NN;
    const __nv_bfloat16* Bp = g_yb + (size_t)(b * CC + mb) * NN;

    float acc[2][8][4];
#pragma unroll
    for (int i = 0; i < 2; i++)
#pragma unroll
        for (int j = 0; j < 8; j++)
#pragma unroll
            for (int q = 0; q < 4; q++) acc[i][j][q] = 0.f;

    issue_stage(sb0,          A, Bp, NN, NN,  0, tid); CP_COMMIT();
    issue_stage(sb0 + STG_SZ, A, Bp, NN, NN, 32, tid); CP_COMMIT();

    const int KT = NN / 32;   // 128
    for (int kt = 0; kt < KT; kt++) {
        CP_WAIT1();
        __syncthreads();
        int nk = kt + 2;
        if (nk < KT)
            issue_stage(sb0 + (nk % NSTAGE) * STG_SZ, A, Bp, NN, NN, nk * 32, tid);
        CP_COMMIT();
        uint32_t s = sb0 + (kt % NSTAGE) * STG_SZ;
        compute_tile(s, s + STG_A, wm, wn, lane, acc);
    }

    // direct store of (c,m) tile
    __nv_bfloat16* Mo = g_Mb + (size_t)b * CC * CC;
#pragma unroll
    for (int mt = 0; mt < 2; mt++) {
        int r0 = cb + wm * 32 + mt * 16 + (lane >> 2);
#pragma unroll
        for (int nt = 0; nt < 8; nt++) {
            int col = mb + wn * 64 + nt * 8 + 2 * (lane & 3);
            *(uint32_t*)(Mo + (size_t)r0 * CC + col) =
                pack_bf16x2(acc[mt][nt][0], acc[mt][nt][1]);
            *(uint32_t*)(Mo + (size_t)(r0 + 8) * CC + col) =
                pack_bf16x2(acc[mt][nt][2], acc[mt][nt][3]);
        }
    }

    // mirror: write transposed tile at (mb, cb) via smem bounce
    if (ii != jj) {
        __syncthreads();   // pipeline smem fully consumed by all warps
        __nv_bfloat16* T = (__nv_bfloat16*)dsm;   // [128 c][130 m]
#pragma unroll
        for (int mt = 0; mt < 2; mt++) {
            int r0 = wm * 32 + mt * 16 + (lane >> 2);
#pragma unroll
            for (int nt = 0; nt < 8; nt++) {
                int col = wn * 64 + nt * 8 + 2 * (lane & 3);
                *(uint32_t*)(T + r0 * 130 + col) =
                    pack_bf16x2(acc[mt][nt][0], acc[mt][nt][1]);
                *(uint32_t*)(T + (r0 + 8) * 130 + col) =
                    pack_bf16x2(acc[mt][nt][2], acc[mt][nt][3]);
            }
        }
        __syncthreads();
#pragma unroll
        for (int i = 0; i < 32; i++) {
            int idx = tid + i * 256;         // over 128 m-rows x 64 u32
            int m = idx >> 6, cp2 = (idx & 63) * 2;
            uint32_t v0 = *(const uint16_t*)(T + cp2 * 130 + m);
            uint32_t v1 = *(const uint16_t*)(T + (cp2 + 1) * 130 + m);
            *(uint32_t*)(Mo + (size_t)(mb + m) * CC + cb + cp2) = v0 | (v1 << 16);
        }
    }
}

// ===========================================================================
// Kernel 5: GEMM2  S[c,n] = sum_m Mb[c,m]*xbT[n,m]; fused epilogue:
//   out = x + gamma*tailor[c]*(colsum[n] + rnorm[n]*S[c,n])
// ===========================================================================
__global__ void __launch_bounds__(256, 2) gemm2_mma(const float* __restrict__ x,
                                                    const float* __restrict__ gptr,
                                                    float* __restrict__ out) {
    extern __shared__ __align__(128) char dsm[];
    const uint32_t sb0 = smem_u32(dsm);
    const int tid = threadIdx.x, lane = tid & 31, warp = tid >> 5;
    const int wm = warp & 3, wn = warp >> 2;
    const int b = blockIdx.z, cb = blockIdx.y * 128, nb = blockIdx.x * 128;
    const __nv_bfloat16* A  = g_Mb  + (size_t)(b * CC + cb) * CC;
    const __nv_bfloat16* Bp = g_xbT + ((size_t)b * NN + nb) * CC;

    float acc[2][8][4];
#pragma unroll
    for (int i = 0; i < 2; i++)
#pragma unroll
        for (int j = 0; j < 8; j++)
#pragma unroll
            for (int q = 0; q < 4; q++) acc[i][j][q] = 0.f;

    issue_stage(sb0,          A, Bp, CC, CC,  0, tid); CP_COMMIT();
    issue_stage(sb0 + STG_SZ, A, Bp, CC, CC, 32, tid); CP_COMMIT();

    const int KT = CC / 32;   // 16
    for (int kt = 0; kt < KT; kt++) {
        CP_WAIT1();
        __syncthreads();
        int nk = kt + 2;
        if (nk < KT)
            issue_stage(sb0 + (nk % NSTAGE) * STG_SZ, A, Bp, CC, CC, nk * 32, tid);
        CP_COMMIT();
        uint32_t s = sb0 + (kt % NSTAGE) * STG_SZ;
        compute_tile(s, s + STG_A, wm, wn, lane, acc);
    }

    float gamma = __ldg(gptr);
#pragma unroll
    for (int mt = 0; mt < 2; mt++) {
        int c0 = cb + wm * 32 + mt * 16 + (lane >> 2);
#pragma unroll
        for (int half = 0; half < 2; half++) {
            int c = c0 + half * 8;
            float tg = gamma * g_tailor[b * CC + c];
            const float* xrow = x   + ((size_t)b * CC + c) * NN;
            float*       orow = out + ((size_t)b * CC + c) * NN;
#pragma unroll
            for (int nt = 0; nt < 8; nt++) {
                int n = nb + wn * 64 + nt * 8 + 2 * (lane & 3);
                float Sx = acc[mt][nt][half * 2];
                float Sy = acc[mt][nt][half * 2 + 1];
                float2 cs = *(const float2*)(g_colsum + b * NN + n);
                float2 rn = *(const float2*)(g_rnorm  + b * NN + n);
                float2 xv = *(const float2*)(xrow + n);
                float2 o;
                o.x = fmaf(tg, fmaf(rn.x, Sx, cs.x), xv.x);
                o.y = fmaf(tg, fmaf(rn.y, Sy, cs.y), xv.y);
                *(float2*)(orow + n) = o;
            }
        }
    }
}

// ===========================================================================
extern "C" void kernel_launch(void* const* d_in, const int* in_sizes, int n_in,
                              void* d_out, int out_size) {
    const float* x     = (const float*)d_in[0];
    const float* gamma = (const float*)d_in[1];
    float* out = (float*)d_out;

    cudaFuncSetAttribute(gemm1_mma, cudaFuncAttributeMaxDynamicSharedMemorySize, SM_DYN);
    cudaFuncSetAttribute(gemm2_mma, cudaFuncAttributeMaxDynamicSharedMemorySize, SM_DYN);

    col_stats_kernel<<<(BB * NN) / 256, 256>>>(x);
    convert_kernel<<<dim3(NN / 64, CC / 64, BB), 256>>>(x);
    tailor_kernel<<<BB * CC, 256>>>(x);
    gemm1_mma<<<dim3(10, 1, BB), 256, SM_DYN>>>();
    gemm2_mma<<<dim3(NN / 128, CC / 128, BB), 256, SM_DYN>>>(x, gamma, out);
}

// round 13
// speedup vs baseline: 4.7490x; 1.2699x over previous
#include <cuda_runtime.h>
#include <cuda_bf16.h>
#include <cstdint>

#define BB 16
#define CC 512
#define NN 4096
#define EPSF 1e-6f

// ---------------- device scratch (allocation-free rule) ----------------
__device__ float g_rnorm [BB * NN];
__device__ float g_srn   [BB * NN];      // sqrt(rnorm)
__device__ float g_colsum[BB * NN];
__device__ float g_w2    [BB * NN];      // srn*(cs*rn+eps)  (so x.w == y.w2)
__device__ float g_tailor[BB * CC];
__device__ __nv_bfloat16 g_yb [(size_t)BB * CC * NN];   // bf16(x*sqrt(rn)) [b,c,n]
__device__ __nv_bfloat16 g_xbT[(size_t)BB * NN * CC];   // bf16(x) transp   [b,n,c]
__device__ __nv_bfloat16 g_Mb [(size_t)BB * CC * CC];   // bf16(M)          [b,c,m]
__device__ float g_Mp [(size_t)4 * BB * 10 * 16384];    // split-K partials (41.9MB)

// ---------------- helpers ----------------
__device__ __forceinline__ uint32_t smem_u32(const void* p) {
    uint32_t a;
    asm("{ .reg .u64 t; cvta.to.shared.u64 t, %1; cvt.u32.u64 %0, t; }" : "=r"(a) : "l"(p));
    return a;
}
__device__ __forceinline__ uint32_t pack_bf16x2(float lo, float hi) {
    uint32_t r;
    asm("cvt.rn.bf16x2.f32 %0, %1, %2;" : "=r"(r) : "f"(hi), "f"(lo));
    return r;
}
__device__ __forceinline__ void ldsm_x4(uint32_t& r0, uint32_t& r1, uint32_t& r2,
                                        uint32_t& r3, uint32_t addr) {
    asm volatile("ldmatrix.sync.aligned.m8n8.x4.shared.b16 {%0,%1,%2,%3}, [%4];"
                 : "=r"(r0), "=r"(r1), "=r"(r2), "=r"(r3) : "r"(addr));
}
__device__ __forceinline__ void mma16816(float* c, const uint32_t* a,
                                         uint32_t b0, uint32_t b1) {
    asm volatile(
        "mma.sync.aligned.m16n8k16.row.col.f32.bf16.bf16.f32 "
        "{%0,%1,%2,%3}, {%4,%5,%6,%7}, {%8,%9}, {%0,%1,%2,%3};"
        : "+f"(c[0]), "+f"(c[1]), "+f"(c[2]), "+f"(c[3])
        : "r"(a[0]), "r"(a[1]), "r"(a[2]), "r"(a[3]), "r"(b0), "r"(b1));
}
__device__ __forceinline__ void cp16(uint32_t dst, const void* src) {
    asm volatile("cp.async.cg.shared.global [%0], [%1], 16;" :: "r"(dst), "l"(src));
}
#define CP_COMMIT() asm volatile("cp.async.commit_group;" ::: "memory")
#define CP_WAIT1()  asm volatile("cp.async.wait_group 1;"  ::: "memory")

// BK = 64: smem row = 64 bf16 data + 8 pad = 144 B
#define STG_A   18432u            // 128 * 144
#define STG_SZ  36864u            // A + B per stage
#define NSTAGE  3
#define SM_DYN  (NSTAGE * STG_SZ) // 110592 B -> 2 CTAs/SM

// ===========================================================================
// Kernel 1: per-column stats over channel dim
// ===========================================================================
__global__ void col_stats_kernel(const float* __restrict__ x) {
    int idx = blockIdx.x * blockDim.x + threadIdx.x;   // B*N
    int b = idx >> 12;
    const float* p = x + (size_t)b * CC * NN + (idx & (NN - 1));
    float ss = 0.f, cs = 0.f;
#pragma unroll 8
    for (int c = 0; c < CC; c++) {
        float v = __ldg(p + (size_t)c * NN);
        ss = fmaf(v, v, ss);
        cs += v;
    }
    float rn = rsqrtf(ss);
    float sr = sqrtf(rn);
    g_rnorm[idx]  = rn;
    g_srn[idx]    = sr;
    g_colsum[idx] = cs;
    g_w2[idx]     = sr * fmaf(cs, rn, EPSF);
}

// ===========================================================================
// Kernel 2: convert: yb = bf16(x*srn) [c,n]; xbT = bf16(x) [n,c]. 64x64 tiles.
// ===========================================================================
__global__ void convert_kernel(const float* __restrict__ x) {
    __shared__ float S[64][65];
    int b = blockIdx.z, c0 = blockIdx.y * 64, n0 = blockIdx.x * 64;
    int t = threadIdx.x;
    const float* srn = g_srn + b * NN + n0;
#pragma unroll
    for (int i = 0; i < 4; i++) {
        int idx = t + i * 256;
        int row = idx >> 4, v = idx & 15;
        size_t go = ((size_t)(b * CC + c0 + row)) * NN + n0 + v * 4;
        float4 xv = *(const float4*)(x + go);
        float4 sv = *(const float4*)(srn + v * 4);
        S[row][v * 4 + 0] = xv.x; S[row][v * 4 + 1] = xv.y;
        S[row][v * 4 + 2] = xv.z; S[row][v * 4 + 3] = xv.w;
        uint2 py;
        py.x = pack_bf16x2(xv.x * sv.x, xv.y * sv.y);
        py.y = pack_bf16x2(xv.z * sv.z, xv.w * sv.w);
        *(uint2*)(g_yb + go) = py;
    }
    __syncthreads();
#pragma unroll
    for (int i = 0; i < 8; i++) {
        int idx = t + i * 256;
        int nl = idx >> 5, c2 = (idx & 31) * 2;
        uint32_t p = pack_bf16x2(S[c2][nl], S[c2 + 1][nl]);
        *(uint32_t*)(g_xbT + ((size_t)b * NN + n0 + nl) * CC + c0 + c2) = p;
    }
}

// ===========================================================================
// Kernel 3: tailor[b,c] = 1/(N + <yb[b,c,:], w2[b,:]>)   (reads bf16 y)
// ===========================================================================
__global__ void tailor_kernel() {
    int b = blockIdx.x >> 9;
    const __nv_bfloat16* row = g_yb + (size_t)blockIdx.x * NN;
    const float* w2 = g_w2 + b * NN;
    float s = 0.f;
    for (int n = threadIdx.x * 2; n < NN; n += 512) {
        __nv_bfloat162 y2 = *(const __nv_bfloat162*)(row + n);
        float2 yf = __bfloat1622float2(y2);
        float2 wv = *(const float2*)(w2 + n);
        s = fmaf(yf.x, wv.x, s);
        s = fmaf(yf.y, wv.y, s);
    }
#pragma unroll
    for (int o = 16; o > 0; o >>= 1) s += __shfl_down_sync(0xffffffffu, s, o);
    __shared__ float red[8];
    int lane = threadIdx.x & 31, wid = threadIdx.x >> 5;
    if (lane == 0) red[wid] = s;
    __syncthreads();
    if (threadIdx.x < 32) {
        s = (threadIdx.x < 8) ? red[threadIdx.x] : 0.f;
#pragma unroll
        for (int o = 4; o > 0; o >>= 1) s += __shfl_down_sync(0xffffffffu, s, o);
        if (threadIdx.x == 0) g_tailor[blockIdx.x] = 1.f / ((float)NN + s);
    }
}

// ===========================================================================
// GEMM building blocks: 128x128 tile, BK=64, 8 warps (4x2), warp tile 32x64
// ===========================================================================
__device__ __forceinline__ void issue_stage(uint32_t sbase,
                                            const __nv_bfloat16* __restrict__ A,
                                            const __nv_bfloat16* __restrict__ Bp,
                                            int lda, int ldb, int k0, int tid) {
#pragma unroll
    for (int i = 0; i < 8; i++) {
        int f = tid + i * 256;                 // 0..2047
        int half = f >> 10;                    // 0 = A, 1 = B
        int r = (f >> 3) & 127, ch = f & 7;
        const __nv_bfloat16* src =
            (half ? Bp + (size_t)r * ldb : A + (size_t)r * lda) + k0 + ch * 8;
        cp16(sbase + half * STG_A + r * 144 + ch * 16, src);
    }
}

__device__ __forceinline__ void compute_tile(uint32_t sa, uint32_t sb,
                                             int wm, int wn, int lane,
                                             float acc[2][8][4]) {
    const uint32_t lrow = (lane & 15), lchunk = (lane >> 4) << 4;
#pragma unroll
    for (int ks = 0; ks < 4; ks++) {
        uint32_t a[2][4];
#pragma unroll
        for (int mt = 0; mt < 2; mt++)
            ldsm_x4(a[mt][0], a[mt][1], a[mt][2], a[mt][3],
                    sa + (wm * 32 + mt * 16 + lrow) * 144 + ks * 32 + lchunk);
        uint32_t bf[4][4];
#pragma unroll
        for (int p = 0; p < 4; p++)
            ldsm_x4(bf[p][0], bf[p][1], bf[p][2], bf[p][3],
                    sb + (wn * 64 + p * 16 + lrow) * 144 + ks * 32 + lchunk);
#pragma unroll
        for (int mt = 0; mt < 2; mt++)
#pragma unroll
            for (int nt = 0; nt < 8; nt++)
                mma16816(acc[mt][nt], a[mt],
                         bf[nt >> 1][nt & 1], bf[nt >> 1][(nt & 1) + 2]);
    }
}

// ===========================================================================
// Kernel 4: GEMM1 (symmetric, split-K=4)  M = y.y^T upper-tri tiles,
// fp32 partials -> g_Mp[sp][b][tile][128x128]
// ===========================================================================
__global__ void __launch_bounds__(256, 2) gemm1_mma() {
    extern __shared__ __align__(128) char dsm[];
    const uint32_t sb0 = smem_u32(dsm);
    const int tid = threadIdx.x, lane = tid & 31, warp = tid >> 5;
    const int wm = warp & 3, wn = warp >> 2;
    const int TI[10] = {0,0,0,0,1,1,1,2,2,3};
    const int TJ[10] = {0,1,2,3,1,2,3,2,3,3};
    const int tile = blockIdx.x, sp = blockIdx.y, b = blockIdx.z;
    const int cb = TI[tile] * 128, mb = TJ[tile] * 128;
    const int kbase = sp * 1024;
    const __nv_bfloat16* A  = g_yb + (size_t)(b * CC + cb) * NN;
    const __nv_bfloat16* Bp = g_yb + (size_t)(b * CC + mb) * NN;

    float acc[2][8][4];
#pragma unroll
    for (int i = 0; i < 2; i++)
#pragma unroll
        for (int j = 0; j < 8; j++)
#pragma unroll
            for (int q = 0; q < 4; q++) acc[i][j][q] = 0.f;

    issue_stage(sb0,          A, Bp, NN, NN, kbase,      tid); CP_COMMIT();
    issue_stage(sb0 + STG_SZ, A, Bp, NN, NN, kbase + 64, tid); CP_COMMIT();

    const int KT = 1024 / 64;   // 16
    for (int kt = 0; kt < KT; kt++) {
        CP_WAIT1();
        __syncthreads();
        int nk = kt + 2;
        if (nk < KT)
            issue_stage(sb0 + (nk % NSTAGE) * STG_SZ, A, Bp, NN, NN,
                        kbase + nk * 64, tid);
        CP_COMMIT();
        uint32_t s = sb0 + (kt % NSTAGE) * STG_SZ;
        compute_tile(s, s + STG_A, wm, wn, lane, acc);
    }

    float* Mp = g_Mp + (((size_t)sp * BB + b) * 10 + tile) * 16384;
#pragma unroll
    for (int mt = 0; mt < 2; mt++) {
        int r0 = wm * 32 + mt * 16 + (lane >> 2);
#pragma unroll
        for (int nt = 0; nt < 8; nt++) {
            int col = wn * 64 + nt * 8 + 2 * (lane & 3);
            *(float2*)(Mp + r0 * 128 + col) =
                make_float2(acc[mt][nt][0], acc[mt][nt][1]);
            *(float2*)(Mp + (r0 + 8) * 128 + col) =
                make_float2(acc[mt][nt][2], acc[mt][nt][3]);
        }
    }
}

// ===========================================================================
// Kernel 5: reduce split-K partials -> bf16 Mb (+ mirrored transpose tile)
// grid (4 chunks of 64x64, 10 tiles, BB)
// ===========================================================================
__global__ void __launch_bounds__(256) reduce_mirror() {
    __shared__ float S[64][65];
    const int TI[10] = {0,0,0,0,1,1,1,2,2,3};
    const int TJ[10] = {0,1,2,3,1,2,3,2,3,3};
    const int q = blockIdx.x, t = blockIdx.y, b = blockIdx.z;
    const int ii = TI[t], jj = TJ[t];
    const int qr = q >> 1, qc = q & 1;
    const int tid = threadIdx.x;
    const size_t spstride = (size_t)BB * 10 * 16384;
    const float* base = g_Mp + ((size_t)b * 10 + t) * 16384;
    __nv_bfloat16* Mo = g_Mb + (size_t)b * CC * CC;
    const int cb = ii * 128, mb = jj * 128;

#pragma unroll
    for (int e = 0; e < 8; e++) {
        int idx = tid + e * 256;       // 2048 float2-pairs
        int r = idx >> 5, p = idx & 31;
        int off = (qr * 64 + r) * 128 + qc * 64 + 2 * p;
        float2 s0 = *(const float2*)(base + off);
        float2 s1 = *(const float2*)(base + spstride + off);
        float2 s2 = *(const float2*)(base + 2 * spstride + off);
        float2 s3 = *(const float2*)(base + 3 * spstride + off);
        float sx = s0.x + s1.x + s2.x + s3.x;
        float sy = s0.y + s1.y + s2.y + s3.y;
        *(uint32_t*)(Mo + (size_t)(cb + qr * 64 + r) * CC + mb + qc * 64 + 2 * p) =
            pack_bf16x2(sx, sy);
        S[r][2 * p] = sx; S[r][2 * p + 1] = sy;
    }
    if (ii == jj) return;
    __syncthreads();
#pragma unroll
    for (int e = 0; e < 8; e++) {
        int idx = tid + e * 256;
        int m = idx >> 5, p = idx & 31;
        uint32_t v = pack_bf16x2(S[2 * p][m], S[2 * p + 1][m]);
        *(uint32_t*)(Mo + (size_t)(mb + qc * 64 + m) * CC + cb + qr * 64 + 2 * p) = v;
    }
}

// ===========================================================================
// Kernel 6: GEMM2  S[c,n] = sum_m Mb[c,m]*xbT[n,m]; fused epilogue:
//   out = x + gamma*tailor[c]*(colsum[n] + rnorm[n]*S[c,n])
// ===========================================================================
__global__ void __launch_bounds__(256, 2) gemm2_mma(const float* __restrict__ x,
                                                    const float* __restrict__ gptr,
                                                    float* __restrict__ out) {
    extern __shared__ __align__(128) char dsm[];
    const uint32_t sb0 = smem_u32(dsm);
    const int tid = threadIdx.x, lane = tid & 31, warp = tid >> 5;
    const int wm = warp & 3, wn = warp >> 2;
    const int b = blockIdx.z, cb = blockIdx.y * 128, nb = blockIdx.x * 128;
    const __nv_bfloat16* A  = g_Mb  + (size_t)(b * CC + cb) * CC;
    const __nv_bfloat16* Bp = g_xbT + ((size_t)b * NN + nb) * CC;

    float acc[2][8][4];
#pragma unroll
    for (int i = 0; i < 2; i++)
#pragma unroll
        for (int j = 0; j < 8; j++)
#pragma unroll
            for (int q = 0; q < 4; q++) acc[i][j][q] = 0.f;

    issue_stage(sb0,          A, Bp, CC, CC,  0, tid); CP_COMMIT();
    issue_stage(sb0 + STG_SZ, A, Bp, CC, CC, 64, tid); CP_COMMIT();

    const int KT = CC / 64;   // 8
    for (int kt = 0; kt < KT; kt++) {
        CP_WAIT1();
        __syncthreads();
        int nk = kt + 2;
        if (nk < KT)
            issue_stage(sb0 + (nk % NSTAGE) * STG_SZ, A, Bp, CC, CC, nk * 64, tid);
        CP_COMMIT();
        uint32_t s = sb0 + (kt % NSTAGE) * STG_SZ;
        compute_tile(s, s + STG_A, wm, wn, lane, acc);
    }

    float gamma = __ldg(gptr);
#pragma unroll
    for (int mt = 0; mt < 2; mt++) {
        int c0 = cb + wm * 32 + mt * 16 + (lane >> 2);
#pragma unroll
        for (int half = 0; half < 2; half++) {
            int c = c0 + half * 8;
            float tg = gamma * g_tailor[b * CC + c];
            const float* xrow = x   + ((size_t)b * CC + c) * NN;
            float*       orow = out + ((size_t)b * CC + c) * NN;
#pragma unroll
            for (int nt = 0; nt < 8; nt++) {
                int n = nb + wn * 64 + nt * 8 + 2 * (lane & 3);
                float Sx = acc[mt][nt][half * 2];
                float Sy = acc[mt][nt][half * 2 + 1];
                float2 cs = *(const float2*)(g_colsum + b * NN + n);
                float2 rn = *(const float2*)(g_rnorm  + b * NN + n);
                float2 xv = *(const float2*)(xrow + n);
                float2 o;
                o.x = fmaf(tg, fmaf(rn.x, Sx, cs.x), xv.x);
                o.y = fmaf(tg, fmaf(rn.y, Sy, cs.y), xv.y);
                *(float2*)(orow + n) = o;
            }
        }
    }
}

// ===========================================================================
extern "C" void kernel_launch(void* const* d_in, const int* in_sizes, int n_in,
                              void* d_out, int out_size) {
    const float* x     = (const float*)d_in[0];
    const float* gamma = (const float*)d_in[1];
    float* out = (float*)d_out;

    cudaFuncSetAttribute(gemm1_mma, cudaFuncAttributeMaxDynamicSharedMemorySize, SM_DYN);
    cudaFuncSetAttribute(gemm2_mma, cudaFuncAttributeMaxDynamicSharedMemorySize, SM_DYN);

    col_stats_kernel<<<(BB * NN) / 256, 256>>>(x);
    convert_kernel<<<dim3(NN / 64, CC / 64, BB), 256>>>(x);
    tailor_kernel<<<BB * CC, 256>>>();
    gemm1_mma<<<dim3(10, 4, BB), 256, SM_DYN>>>();
    reduce_mirror<<<dim3(4, 10, BB), 256>>>();
    gemm2_mma<<<dim3(NN / 128, CC / 128, BB), 256, SM_DYN>>>(x, gamma, out);
}

// round 14
// speedup vs baseline: 5.0861x; 1.0710x over previous
#include <cuda_runtime.h>
#include <cuda_bf16.h>
#include <cstdint>

#define BB 16
#define CC 512
#define NN 4096
#define EPSF 1e-6f

// ---------------- device scratch (allocation-free rule) ----------------
__device__ float g_rnorm [BB * NN];
__device__ float g_srn   [BB * NN];      // sqrt(rnorm)
__device__ float g_colsum[BB * NN];
__device__ float g_w2    [BB * NN];      // srn*(cs*rn+eps)  (so x.w == y.w2)
__device__ float g_tailor[BB * CC];
__device__ __nv_bfloat16 g_yb [(size_t)BB * CC * NN];   // bf16(x*sqrt(rn)) [b,c,n]
__device__ __nv_bfloat16 g_Mb [(size_t)BB * CC * CC];   // bf16(M)          [b,c,m]
__device__ float g_Mp [(size_t)4 * BB * 10 * 16384];    // split-K partials

// ---------------- helpers ----------------
__device__ __forceinline__ uint32_t smem_u32(const void* p) {
    uint32_t a;
    asm("{ .reg .u64 t; cvta.to.shared.u64 t, %1; cvt.u32.u64 %0, t; }" : "=r"(a) : "l"(p));
    return a;
}
__device__ __forceinline__ uint32_t pack_bf16x2(float lo, float hi) {
    uint32_t r;
    asm("cvt.rn.bf16x2.f32 %0, %1, %2;" : "=r"(r) : "f"(hi), "f"(lo));
    return r;
}
__device__ __forceinline__ void ldsm_x4(uint32_t& r0, uint32_t& r1, uint32_t& r2,
                                        uint32_t& r3, uint32_t addr) {
    asm volatile("ldmatrix.sync.aligned.m8n8.x4.shared.b16 {%0,%1,%2,%3}, [%4];"
                 : "=r"(r0), "=r"(r1), "=r"(r2), "=r"(r3) : "r"(addr));
}
__device__ __forceinline__ void ldsm_x4_t(uint32_t& r0, uint32_t& r1, uint32_t& r2,
                                          uint32_t& r3, uint32_t addr) {
    asm volatile("ldmatrix.sync.aligned.m8n8.x4.trans.shared.b16 {%0,%1,%2,%3}, [%4];"
                 : "=r"(r0), "=r"(r1), "=r"(r2), "=r"(r3) : "r"(addr));
}
__device__ __forceinline__ void mma16816(float* c, const uint32_t* a,
                                         uint32_t b0, uint32_t b1) {
    asm volatile(
        "mma.sync.aligned.m16n8k16.row.col.f32.bf16.bf16.f32 "
        "{%0,%1,%2,%3}, {%4,%5,%6,%7}, {%8,%9}, {%0,%1,%2,%3};"
        : "+f"(c[0]), "+f"(c[1]), "+f"(c[2]), "+f"(c[3])
        : "r"(a[0]), "r"(a[1]), "r"(a[2]), "r"(a[3]), "r"(b0), "r"(b1));
}
__device__ __forceinline__ void cp16(uint32_t dst, const void* src) {
    asm volatile("cp.async.cg.shared.global [%0], [%1], 16;" :: "r"(dst), "l"(src));
}
#define CP_COMMIT() asm volatile("cp.async.commit_group;" ::: "memory")
#define CP_WAIT1()  asm volatile("cp.async.wait_group 1;"  ::: "memory")

// A stage (both GEMMs): 128 rows x (64 bf16 + 8 pad) = 144 B/row
#define STG_A    18432u
// GEMM1 B stage: 128 rows x 144 B  |  GEMM2 B stage: 64 rows x 272 B
#define STG1_SZ  36864u
#define STG2_SZ  35840u
#define NSTAGE   3
#define SM_DYN1  (NSTAGE * STG1_SZ)   // 110592
#define SM_DYN2  (NSTAGE * STG2_SZ)   // 107520

// ===========================================================================
// Kernel 1: per-column stats over channel dim
// ===========================================================================
__global__ void col_stats_kernel(const float* __restrict__ x) {
    int idx = blockIdx.x * blockDim.x + threadIdx.x;   // B*N
    int b = idx >> 12;
    const float* p = x + (size_t)b * CC * NN + (idx & (NN - 1));
    float ss = 0.f, cs = 0.f;
#pragma unroll 8
    for (int c = 0; c < CC; c++) {
        float v = __ldg(p + (size_t)c * NN);
        ss = fmaf(v, v, ss);
        cs += v;
    }
    float rn = rsqrtf(ss);
    float sr = sqrtf(rn);
    g_rnorm[idx]  = rn;
    g_srn[idx]    = sr;
    g_colsum[idx] = cs;
    g_w2[idx]     = sr * fmaf(cs, rn, EPSF);
}

// ===========================================================================
// Kernel 2: convert (elementwise): yb = bf16(x * srn[n])
// ===========================================================================
__global__ void convert_kernel(const float* __restrict__ x) {
    size_t i = ((size_t)blockIdx.x * 256 + threadIdx.x) * 8;
    int n = (int)(i & (NN - 1));
    int b = (int)(i >> 21);                 // / (CC*NN)
    const float* sp = g_srn + b * NN + n;
    float4 x0 = *(const float4*)(x + i);
    float4 x1 = *(const float4*)(x + i + 4);
    float4 s0 = *(const float4*)sp;
    float4 s1 = *(const float4*)(sp + 4);
    uint4 o;
    o.x = pack_bf16x2(x0.x * s0.x, x0.y * s0.y);
    o.y = pack_bf16x2(x0.z * s0.z, x0.w * s0.w);
    o.z = pack_bf16x2(x1.x * s1.x, x1.y * s1.y);
    o.w = pack_bf16x2(x1.z * s1.z, x1.w * s1.w);
    *(uint4*)(g_yb + i) = o;
}

// ===========================================================================
// Kernel 3: tailor[b,c] = 1/(N + <yb[b,c,:], w2[b,:]>)
// ===========================================================================
__global__ void tailor_kernel() {
    int b = blockIdx.x >> 9;
    const __nv_bfloat16* row = g_yb + (size_t)blockIdx.x * NN;
    const float* w2 = g_w2 + b * NN;
    float s = 0.f;
    for (int n = threadIdx.x * 2; n < NN; n += 512) {
        __nv_bfloat162 y2 = *(const __nv_bfloat162*)(row + n);
        float2 yf = __bfloat1622float2(y2);
        float2 wv = *(const float2*)(w2 + n);
        s = fmaf(yf.x, wv.x, s);
        s = fmaf(yf.y, wv.y, s);
    }
#pragma unroll
    for (int o = 16; o > 0; o >>= 1) s += __shfl_down_sync(0xffffffffu, s, o);
    __shared__ float red[8];
    int lane = threadIdx.x & 31, wid = threadIdx.x >> 5;
    if (lane == 0) red[wid] = s;
    __syncthreads();
    if (threadIdx.x < 32) {
        s = (threadIdx.x < 8) ? red[threadIdx.x] : 0.f;
#pragma unroll
        for (int o = 4; o > 0; o >>= 1) s += __shfl_down_sync(0xffffffffu, s, o);
        if (threadIdx.x == 0) g_tailor[blockIdx.x] = 1.f / ((float)NN + s);
    }
}

// ===========================================================================
// Fragment loaders
// ===========================================================================
__device__ __forceinline__ void lda_frag(uint32_t a[2][4], uint32_t sa,
                                         int wm, int lane, int ks) {
    const uint32_t lrow = lane & 15, lch = (lane >> 4) << 4;
#pragma unroll
    for (int mt = 0; mt < 2; mt++)
        ldsm_x4(a[mt][0], a[mt][1], a[mt][2], a[mt][3],
                sa + (wm * 32 + mt * 16 + lrow) * 144 + ks * 32 + lch);
}
// GEMM1 B: [n_out rows][k], non-trans
__device__ __forceinline__ void ldb_nt(uint32_t bf[4], uint32_t sb,
                                       int wn, int lane, int ks, int p) {
    const uint32_t lrow = lane & 15, lch = (lane >> 4) << 4;
    ldsm_x4(bf[0], bf[1], bf[2], bf[3],
            sb + (wn * 64 + p * 16 + lrow) * 144 + ks * 32 + lch);
}
// GEMM2 B: [k rows][n_out], trans. row = k (272B stride), col = n chunk.
__device__ __forceinline__ void ldb_tr(uint32_t bf[4], uint32_t sb,
                                       int wn, int lane, int ks, int p) {
    uint32_t addr = sb + (ks * 16 + (lane & 15)) * 272
                       + (wn * 64 + p * 16 + ((lane >> 4) << 3)) * 2;
    ldsm_x4_t(bf[0], bf[1], bf[2], bf[3], addr);
}
__device__ __forceinline__ void mma_group_nt(float acc[2][8][4], uint32_t a[2][4],
                                             uint32_t bf[4], int p) {
#pragma unroll
    for (int mt = 0; mt < 2; mt++) {
        mma16816(acc[mt][2 * p],     a[mt], bf[0], bf[2]);
        mma16816(acc[mt][2 * p + 1], a[mt], bf[1], bf[3]);
    }
}
__device__ __forceinline__ void mma_group_tr(float acc[2][8][4], uint32_t a[2][4],
                                             uint32_t bf[4], int p) {
#pragma unroll
    for (int mt = 0; mt < 2; mt++) {
        mma16816(acc[mt][2 * p],     a[mt], bf[0], bf[1]);
        mma16816(acc[mt][2 * p + 1], a[mt], bf[2], bf[3]);
    }
}

// ===========================================================================
// Kernel 4: GEMM1 (symmetric, split-K=4)  M = y.y^T upper-tri tiles
// ===========================================================================
__global__ void __launch_bounds__(256, 2) gemm1_mma() {
    extern __shared__ __align__(128) char dsm[];
    const uint32_t sb0 = smem_u32(dsm);
    const int tid = threadIdx.x, lane = tid & 31, warp = tid >> 5;
    const int wm = warp & 3, wn = warp >> 2;
    const int TI[10] = {0,0,0,0,1,1,1,2,2,3};
    const int TJ[10] = {0,1,2,3,1,2,3,2,3,3};
    const int tile = blockIdx.x, sp = blockIdx.y, b = blockIdx.z;
    const int cb = TI[tile] * 128, mb = TJ[tile] * 128;
    const int kbase = sp * 1024;
    const __nv_bfloat16* A  = g_yb + (size_t)(b * CC + cb) * NN;
    const __nv_bfloat16* Bp = g_yb + (size_t)(b * CC + mb) * NN;

    float acc[2][8][4];
#pragma unroll
    for (int i = 0; i < 2; i++)
#pragma unroll
        for (int j = 0; j < 8; j++)
#pragma unroll
            for (int q = 0; q < 4; q++) acc[i][j][q] = 0.f;

    // stage issue: A 128x64 + B 128x64, both 144B rows
    auto issue = [&](uint32_t sbase, int k0) {
#pragma unroll
        for (int i = 0; i < 8; i++) {
            int f = tid + i * 256;
            int half = f >> 10;
            int r = (f >> 3) & 127, ch = f & 7;
            const __nv_bfloat16* src =
                (half ? Bp + (size_t)r * NN : A + (size_t)r * NN) + k0 + ch * 8;
            cp16(sbase + half * STG_A + r * 144 + ch * 16, src);
        }
    };

    issue(sb0,           kbase);      CP_COMMIT();
    issue(sb0 + STG1_SZ, kbase + 64); CP_COMMIT();

    const int KT = 16;
    for (int kt = 0; kt < KT; kt++) {
        CP_WAIT1();
        __syncthreads();
        int nk = kt + 2;
        if (nk < KT) issue(sb0 + (nk % NSTAGE) * STG1_SZ, kbase + nk * 64);
        CP_COMMIT();
        uint32_t sa = sb0 + (kt % NSTAGE) * STG1_SZ;
        uint32_t sbB = sa + STG_A;

        uint32_t a[2][2][4], bf[2][4];
        lda_frag(a[0], sa, wm, lane, 0);
        ldb_nt(bf[0], sbB, wn, lane, 0, 0);
#pragma unroll
        for (int ks = 0; ks < 4; ks++) {
#pragma unroll
            for (int p = 0; p < 4; p++) {
                int cur = (ks * 4 + p) & 1, nxt = cur ^ 1;
                if (p < 3) ldb_nt(bf[nxt], sbB, wn, lane, ks, p + 1);
                else if (ks < 3) {
                    ldb_nt(bf[nxt], sbB, wn, lane, ks + 1, 0);
                    lda_frag(a[(ks + 1) & 1], sa, wm, lane, ks + 1);
                }
                mma_group_nt(acc, a[ks & 1], bf[cur], p);
            }
        }
    }

    float* Mp = g_Mp + (((size_t)sp * BB + b) * 10 + tile) * 16384;
#pragma unroll
    for (int mt = 0; mt < 2; mt++) {
        int r0 = wm * 32 + mt * 16 + (lane >> 2);
#pragma unroll
        for (int nt = 0; nt < 8; nt++) {
            int col = wn * 64 + nt * 8 + 2 * (lane & 3);
            *(float2*)(Mp + r0 * 128 + col) =
                make_float2(acc[mt][nt][0], acc[mt][nt][1]);
            *(float2*)(Mp + (r0 + 8) * 128 + col) =
                make_float2(acc[mt][nt][2], acc[mt][nt][3]);
        }
    }
}

// ===========================================================================
// Kernel 5: reduce split-K partials -> bf16 Mb (+ mirrored transpose tile)
// ===========================================================================
__global__ void __launch_bounds__(256) reduce_mirror() {
    __shared__ float S[64][65];
    const int TI[10] = {0,0,0,0,1,1,1,2,2,3};
    const int TJ[10] = {0,1,2,3,1,2,3,2,3,3};
    const int q = blockIdx.x, t = blockIdx.y, b = blockIdx.z;
    const int ii = TI[t], jj = TJ[t];
    const int qr = q >> 1, qc = q & 1;
    const int tid = threadIdx.x;
    const size_t spstride = (size_t)BB * 10 * 16384;
    const float* base = g_Mp + ((size_t)b * 10 + t) * 16384;
    __nv_bfloat16* Mo = g_Mb + (size_t)b * CC * CC;
    const int cb = ii * 128, mb = jj * 128;

#pragma unroll
    for (int e = 0; e < 8; e++) {
        int idx = tid + e * 256;
        int r = idx >> 5, p = idx & 31;
        int off = (qr * 64 + r) * 128 + qc * 64 + 2 * p;
        float2 s0 = *(const float2*)(base + off);
        float2 s1 = *(const float2*)(base + spstride + off);
        float2 s2 = *(const float2*)(base + 2 * spstride + off);
        float2 s3 = *(const float2*)(base + 3 * spstride + off);
        float sx = s0.x + s1.x + s2.x + s3.x;
        float sy = s0.y + s1.y + s2.y + s3.y;
        *(uint32_t*)(Mo + (size_t)(cb + qr * 64 + r) * CC + mb + qc * 64 + 2 * p) =
            pack_bf16x2(sx, sy);
        S[r][2 * p] = sx; S[r][2 * p + 1] = sy;
    }
    if (ii == jj) return;
    __syncthreads();
#pragma unroll
    for (int e = 0; e < 8; e++) {
        int idx = tid + e * 256;
        int m = idx >> 5, p = idx & 31;
        uint32_t v = pack_bf16x2(S[2 * p][m], S[2 * p + 1][m]);
        *(uint32_t*)(Mo + (size_t)(mb + qc * 64 + m) * CC + cb + qr * 64 + 2 * p) = v;
    }
}

// ===========================================================================
// Kernel 6: GEMM2  S'[c,n] = sum_m Mb[c,m]*yb[m,n]; epilogue:
//   out = x + gamma*tailor[c]*(colsum[n] + srn[n]*S'[c,n])
// (yb = x*srn  =>  S' = srn*S  =>  rn*S == srn*S')
// ===========================================================================
__global__ void __launch_bounds__(256, 2) gemm2_mma(const float* __restrict__ x,
                                                    const float* __restrict__ gptr,
                                                    float* __restrict__ out) {
    extern __shared__ __align__(128) char dsm[];
    const uint32_t sb0 = smem_u32(dsm);
    const int tid = threadIdx.x, lane = tid & 31, warp = tid >> 5;
    const int wm = warp & 3, wn = warp >> 2;
    const int b = blockIdx.z, cb = blockIdx.y * 128, nb = blockIdx.x * 128;
    const __nv_bfloat16* A  = g_Mb + (size_t)(b * CC + cb) * CC;
    const __nv_bfloat16* Bp = g_yb + (size_t)b * CC * NN;   // rows = channel (k)

    float acc[2][8][4];
#pragma unroll
    for (int i = 0; i < 2; i++)
#pragma unroll
        for (int j = 0; j < 8; j++)
#pragma unroll
            for (int q = 0; q < 4; q++) acc[i][j][q] = 0.f;

    // stage: A 128 rows x 144B; B 64 k-rows x 272B (128 n + 16B pad)
    auto issue = [&](uint32_t sbase, int k0) {
#pragma unroll
        for (int i = 0; i < 8; i++) {
            int f = tid + i * 256;
            if (f < 1024) {
                int r = f >> 3, ch = f & 7;
                cp16(sbase + r * 144 + ch * 16, A + (size_t)r * CC + k0 + ch * 8);
            } else {
                int g = f - 1024;
                int r = g >> 4, ch = g & 15;
                cp16(sbase + STG_A + r * 272 + ch * 16,
                     Bp + (size_t)(k0 + r) * NN + nb + ch * 8);
            }
        }
    };

    issue(sb0,            0); CP_COMMIT();
    issue(sb0 + STG2_SZ, 64); CP_COMMIT();

    const int KT = CC / 64;   // 8
    for (int kt = 0; kt < KT; kt++) {
        CP_WAIT1();
        __syncthreads();
        int nk = kt + 2;
        if (nk < KT) issue(sb0 + (nk % NSTAGE) * STG2_SZ, nk * 64);
        CP_COMMIT();
        uint32_t sa = sb0 + (kt % NSTAGE) * STG2_SZ;
        uint32_t sbB = sa + STG_A;

        uint32_t a[2][2][4], bf[2][4];
        lda_frag(a[0], sa, wm, lane, 0);
        ldb_tr(bf[0], sbB, wn, lane, 0, 0);
#pragma unroll
        for (int ks = 0; ks < 4; ks++) {
#pragma unroll
            for (int p = 0; p < 4; p++) {
                int cur = (ks * 4 + p) & 1, nxt = cur ^ 1;
                if (p < 3) ldb_tr(bf[nxt], sbB, wn, lane, ks, p + 1);
                else if (ks < 3) {
                    ldb_tr(bf[nxt], sbB, wn, lane, ks + 1, 0);
                    lda_frag(a[(ks + 1) & 1], sa, wm, lane, ks + 1);
                }
                mma_group_tr(acc, a[ks & 1], bf[cur], p);
            }
        }
    }

    float gamma = __ldg(gptr);
#pragma unroll
    for (int mt = 0; mt < 2; mt++) {
        int c0 = cb + wm * 32 + mt * 16 + (lane >> 2);
#pragma unroll
        for (int half = 0; half < 2; half++) {
            int c = c0 + half * 8;
            float tg = gamma * g_tailor[b * CC + c];
            const float* xrow = x   + ((size_t)b * CC + c) * NN;
            float*       orow = out + ((size_t)b * CC + c) * NN;
#pragma unroll
            for (int nt = 0; nt < 8; nt++) {
                int n = nb + wn * 64 + nt * 8 + 2 * (lane & 3);
                float Sx = acc[mt][nt][half * 2];
                float Sy = acc[mt][nt][half * 2 + 1];
                float2 cs = *(const float2*)(g_colsum + b * NN + n);
                float2 sr = *(const float2*)(g_srn    + b * NN + n);
                float2 xv = *(const float2*)(xrow + n);
                float2 o;
                o.x = fmaf(tg, fmaf(sr.x, Sx, cs.x), xv.x);
                o.y = fmaf(tg, fmaf(sr.y, Sy, cs.y), xv.y);
                *(float2*)(orow + n) = o;
            }
        }
    }
}

// ===========================================================================
extern "C" void kernel_launch(void* const* d_in, const int* in_sizes, int n_in,
                              void* d_out, int out_size) {
    const float* x     = (const float*)d_in[0];
    const float* gamma = (const float*)d_in[1];
    float* out = (float*)d_out;

    cudaFuncSetAttribute(gemm1_mma, cudaFuncAttributeMaxDynamicSharedMemorySize, SM_DYN1);
    cudaFuncSetAttribute(gemm2_mma, cudaFuncAttributeMaxDynamicSharedMemorySize, SM_DYN2);

    col_stats_kernel<<<(BB * NN) / 256, 256>>>(x);
    convert_kernel<<<(int)(((size_t)BB * CC * NN) / (256 * 8)), 256>>>(x);
    tailor_kernel<<<BB * CC, 256>>>();
    gemm1_mma<<<dim3(10, 4, BB), 256, SM_DYN1>>>();
    reduce_mirror<<<dim3(4, 10, BB), 256>>>();
    gemm2_mma<<<dim3(NN / 128, CC / 128, BB), 256, SM_DYN2>>>(x, gamma, out);
}

// round 15
// speedup vs baseline: 5.3565x; 1.0532x over previous
#include <cuda_runtime.h>
#include <cuda_bf16.h>
#include <cstdint>

#define BB 16
#define CC 512
#define NN 4096
#define EPSF 1e-6f

// ---------------- device scratch (allocation-free rule) ----------------
__device__ float g_rnorm [BB * NN];
__device__ float g_srn   [BB * NN];      // sqrt(rnorm)
__device__ float g_colsum[BB * NN];
__device__ float g_w     [BB * NN];      // rn*(cs*rn+eps)
__device__ float g_tacc  [BB * CC];      // tailor accumulators (atomic)
__device__ uint8_t g_y8 [(size_t)BB * CC * NN];   // e4m3(x*srn) [b,c,n]
__device__ uint8_t g_y8T[(size_t)BB * NN * CC];   // e4m3(x*srn) [b,n,c]
__device__ uint8_t g_Mb8[(size_t)BB * CC * CC];   // e4m3(M)     [b,c,m]
__device__ float g_Mp [(size_t)4 * BB * 10 * 16384];  // split-K partials

// ---------------- helpers ----------------
__device__ __forceinline__ uint32_t smem_u32(const void* p) {
    uint32_t a;
    asm("{ .reg .u64 t; cvta.to.shared.u64 t, %1; cvt.u32.u64 %0, t; }" : "=r"(a) : "l"(p));
    return a;
}
__device__ __forceinline__ uint16_t pack_e4m3x2(float lo, float hi) {
    uint16_t r;
    asm("cvt.rn.satfinite.e4m3x2.f32 %0, %1, %2;" : "=h"(r) : "f"(hi), "f"(lo));
    return r;
}
__device__ __forceinline__ uint32_t pack_e4m3x4(float f0, float f1, float f2, float f3) {
    uint16_t lo = pack_e4m3x2(f0, f1);
    uint16_t hi = pack_e4m3x2(f2, f3);
    return (uint32_t)lo | ((uint32_t)hi << 16);
}
__device__ __forceinline__ void ldsm_x4(uint32_t& r0, uint32_t& r1, uint32_t& r2,
                                        uint32_t& r3, uint32_t addr) {
    asm volatile("ldmatrix.sync.aligned.m8n8.x4.shared.b16 {%0,%1,%2,%3}, [%4];"
                 : "=r"(r0), "=r"(r1), "=r"(r2), "=r"(r3) : "r"(addr));
}
// fp8 e4m3 MMA, m16n8k32, fp32 accum
__device__ __forceinline__ void mma_fp8(float* c, const uint32_t* a,
                                        uint32_t b0, uint32_t b1) {
    asm volatile(
        "mma.sync.aligned.m16n8k32.row.col.f32.e4m3.e4m3.f32 "
        "{%0,%1,%2,%3}, {%4,%5,%6,%7}, {%8,%9}, {%0,%1,%2,%3};"
        : "+f"(c[0]), "+f"(c[1]), "+f"(c[2]), "+f"(c[3])
        : "r"(a[0]), "r"(a[1]), "r"(a[2]), "r"(a[3]), "r"(b0), "r"(b1));
}
__device__ __forceinline__ void cp16(uint32_t dst, const void* src) {
    asm volatile("cp.async.cg.shared.global [%0], [%1], 16;" :: "r"(dst), "l"(src));
}
#define CP_COMMIT() asm volatile("cp.async.commit_group;" ::: "memory")
#define CP_WAIT1()  asm volatile("cp.async.wait_group 1;"  ::: "memory")

// tiles 128x128, BK = 128 fp8 elems (128 B) ; smem row = 128 + 16 pad = 144 B
#define STG_A    18432u            // 128 * 144
#define STG_SZ   36864u            // A + B per stage
#define NSTAGE   3
#define SM_DYN   (NSTAGE * STG_SZ) // 110592 -> 2 CTAs/SM (reg-capped anyway)

// ===========================================================================
// Kernel 1: per-column stats over channel dim (+ zero tailor accumulators)
// ===========================================================================
__global__ void col_stats_kernel(const float* __restrict__ x) {
    int idx = blockIdx.x * blockDim.x + threadIdx.x;   // B*N
    if (idx < BB * CC) g_tacc[idx] = 0.f;
    int b = idx >> 12;
    const float* p = x + (size_t)b * CC * NN + (idx & (NN - 1));
    float ss = 0.f, cs = 0.f;
#pragma unroll 8
    for (int c = 0; c < CC; c++) {
        float v = __ldg(p + (size_t)c * NN);
        ss = fmaf(v, v, ss);
        cs += v;
    }
    float rn = rsqrtf(ss);
    g_rnorm[idx]  = rn;
    g_srn[idx]    = sqrtf(rn);
    g_colsum[idx] = cs;
    g_w[idx]      = rn * fmaf(cs, rn, EPSF);
}

// ===========================================================================
// Kernel 2: convert 64x64 tiles: y8 = e4m3(x*srn) [c,n]; y8T [n,c];
//           + exact fp32 tailor partials: atomicAdd(<x_row, w>) per (b,c)
// ===========================================================================
__global__ void convert_kernel(const float* __restrict__ x) {
    __shared__ float S[64][65];
    int b = blockIdx.z, c0 = blockIdx.y * 64, n0 = blockIdx.x * 64;
    int t = threadIdx.x;
    const float* srn = g_srn + b * NN + n0;
    const float* wr  = g_w   + b * NN + n0;
#pragma unroll
    for (int i = 0; i < 4; i++) {
        int idx = t + i * 256;
        int row = idx >> 4, v = idx & 15;
        size_t go = ((size_t)(b * CC + c0 + row)) * NN + n0 + v * 4;
        float4 xv = *(const float4*)(x + go);
        float4 sv = *(const float4*)(srn + v * 4);
        float4 wv = *(const float4*)(wr + v * 4);
        float y0 = xv.x * sv.x, y1 = xv.y * sv.y;
        float y2 = xv.z * sv.z, y3 = xv.w * sv.w;
        S[row][v * 4 + 0] = y0; S[row][v * 4 + 1] = y1;
        S[row][v * 4 + 2] = y2; S[row][v * 4 + 3] = y3;
        *(uint32_t*)(g_y8 + go) = pack_e4m3x4(y0, y1, y2, y3);
        // tailor partial: exact fp32 dot with w
        float d = fmaf(xv.x, wv.x, fmaf(xv.y, wv.y,
                  fmaf(xv.z, wv.z, xv.w * wv.w)));
#pragma unroll
        for (int o = 8; o > 0; o >>= 1)
            d += __shfl_down_sync(0xffffffffu, d, o, 16);
        if ((t & 15) == 0)
            atomicAdd(&g_tacc[b * CC + c0 + row], d);
    }
    __syncthreads();
#pragma unroll
    for (int i = 0; i < 4; i++) {
        int idx = t + i * 256;
        int nl = idx >> 4, c4 = (idx & 15) * 4;
        uint32_t p = pack_e4m3x4(S[c4][nl], S[c4 + 1][nl],
                                 S[c4 + 2][nl], S[c4 + 3][nl]);
        *(uint32_t*)(g_y8T + ((size_t)b * NN + n0 + nl) * CC + c0 + c4) = p;
    }
}

// ===========================================================================
// Fragment loaders (byte addressing identical to bf16 version; k-step = 32 B)
// ===========================================================================
__device__ __forceinline__ void lda_frag(uint32_t a[2][4], uint32_t sa,
                                         int wm, int lane, int ks) {
    const uint32_t lrow = lane & 15, lch = (lane >> 4) << 4;
#pragma unroll
    for (int mt = 0; mt < 2; mt++)
        ldsm_x4(a[mt][0], a[mt][1], a[mt][2], a[mt][3],
                sa + (wm * 32 + mt * 16 + lrow) * 144 + ks * 32 + lch);
}
__device__ __forceinline__ void ldb_nt(uint32_t bf[4], uint32_t sb,
                                       int wn, int lane, int ks, int p) {
    const uint32_t lrow = lane & 15, lch = (lane >> 4) << 4;
    ldsm_x4(bf[0], bf[1], bf[2], bf[3],
            sb + (wn * 64 + p * 16 + lrow) * 144 + ks * 32 + lch);
}
__device__ __forceinline__ void mma_group(float acc[2][8][4], uint32_t a[2][4],
                                          uint32_t bf[4], int p) {
#pragma unroll
    for (int mt = 0; mt < 2; mt++) {
        mma_fp8(acc[mt][2 * p],     a[mt], bf[0], bf[2]);
        mma_fp8(acc[mt][2 * p + 1], a[mt], bf[1], bf[3]);
    }
}

// shared fp8 mainloop body (one K-stage: 4 ks of k32)
__device__ __forceinline__ void compute_stage(uint32_t sa, uint32_t sbB,
                                              int wm, int wn, int lane,
                                              float acc[2][8][4]) {
    uint32_t a[2][2][4], bf[2][4];
    lda_frag(a[0], sa, wm, lane, 0);
    ldb_nt(bf[0], sbB, wn, lane, 0, 0);
#pragma unroll
    for (int ks = 0; ks < 4; ks++) {
#pragma unroll
        for (int p = 0; p < 4; p++) {
            int cur = (ks * 4 + p) & 1, nxt = cur ^ 1;
            if (p < 3) ldb_nt(bf[nxt], sbB, wn, lane, ks, p + 1);
            else if (ks < 3) {
                ldb_nt(bf[nxt], sbB, wn, lane, ks + 1, 0);
                lda_frag(a[(ks + 1) & 1], sa, wm, lane, ks + 1);
            }
            mma_group(acc, a[ks & 1], bf[cur], p);
        }
    }
}

// ===========================================================================
// Kernel 3: GEMM1 (symmetric, split-K=4)  M = y.y^T upper-tri tiles, fp8
// ===========================================================================
__global__ void __launch_bounds__(256, 2) gemm1_mma() {
    extern __shared__ __align__(128) char dsm[];
    const uint32_t sb0 = smem_u32(dsm);
    const int tid = threadIdx.x, lane = tid & 31, warp = tid >> 5;
    const int wm = warp & 3, wn = warp >> 2;
    const int TI[10] = {0,0,0,0,1,1,1,2,2,3};
    const int TJ[10] = {0,1,2,3,1,2,3,2,3,3};
    const int tile = blockIdx.x, sp = blockIdx.y, b = blockIdx.z;
    const int cb = TI[tile] * 128, mb = TJ[tile] * 128;
    const int kbase = sp * 1024;            // bytes == elements (fp8)
    const uint8_t* A  = g_y8 + (size_t)(b * CC + cb) * NN;
    const uint8_t* Bp = g_y8 + (size_t)(b * CC + mb) * NN;

    float acc[2][8][4];
#pragma unroll
    for (int i = 0; i < 2; i++)
#pragma unroll
        for (int j = 0; j < 8; j++)
#pragma unroll
            for (int q = 0; q < 4; q++) acc[i][j][q] = 0.f;

    auto issue = [&](uint32_t sbase, int k0) {
#pragma unroll
        for (int i = 0; i < 8; i++) {
            int f = tid + i * 256;
            int half = f >> 10;
            int r = (f >> 3) & 127, ch = f & 7;
            const uint8_t* src =
                (half ? Bp + (size_t)r * NN : A + (size_t)r * NN) + k0 + ch * 16;
            cp16(sbase + half * STG_A + r * 144 + ch * 16, src);
        }
    };

    issue(sb0,          kbase);       CP_COMMIT();
    issue(sb0 + STG_SZ, kbase + 128); CP_COMMIT();

    const int KT = 8;    // 1024 / 128
    for (int kt = 0; kt < KT; kt++) {
        CP_WAIT1();
        __syncthreads();
        int nk = kt + 2;
        if (nk < KT) issue(sb0 + (nk % NSTAGE) * STG_SZ, kbase + nk * 128);
        CP_COMMIT();
        uint32_t s = sb0 + (kt % NSTAGE) * STG_SZ;
        compute_stage(s, s + STG_A, wm, wn, lane, acc);
    }

    float* Mp = g_Mp + (((size_t)sp * BB + b) * 10 + tile) * 16384;
#pragma unroll
    for (int mt = 0; mt < 2; mt++) {
        int r0 = wm * 32 + mt * 16 + (lane >> 2);
#pragma unroll
        for (int nt = 0; nt < 8; nt++) {
            int col = wn * 64 + nt * 8 + 2 * (lane & 3);
            *(float2*)(Mp + r0 * 128 + col) =
                make_float2(acc[mt][nt][0], acc[mt][nt][1]);
            *(float2*)(Mp + (r0 + 8) * 128 + col) =
                make_float2(acc[mt][nt][2], acc[mt][nt][3]);
        }
    }
}

// ===========================================================================
// Kernel 4: reduce split-K partials -> fp8 Mb (+ mirrored transpose tile)
// ===========================================================================
__global__ void __launch_bounds__(256) reduce_mirror() {
    __shared__ float S[64][65];
    const int TI[10] = {0,0,0,0,1,1,1,2,2,3};
    const int TJ[10] = {0,1,2,3,1,2,3,2,3,3};
    const int q = blockIdx.x, t = blockIdx.y, b = blockIdx.z;
    const int ii = TI[t], jj = TJ[t];
    const int qr = q >> 1, qc = q & 1;
    const int tid = threadIdx.x;
    const size_t spstride = (size_t)BB * 10 * 16384;
    const float* base = g_Mp + ((size_t)b * 10 + t) * 16384;
    uint8_t* Mo = g_Mb8 + (size_t)b * CC * CC;
    const int cb = ii * 128, mb = jj * 128;

#pragma unroll
    for (int e = 0; e < 8; e++) {
        int idx = tid + e * 256;
        int r = idx >> 5, p = idx & 31;
        int off = (qr * 64 + r) * 128 + qc * 64 + 2 * p;
        float2 s0 = *(const float2*)(base + off);
        float2 s1 = *(const float2*)(base + spstride + off);
        float2 s2 = *(const float2*)(base + 2 * spstride + off);
        float2 s3 = *(const float2*)(base + 3 * spstride + off);
        float sx = s0.x + s1.x + s2.x + s3.x;
        float sy = s0.y + s1.y + s2.y + s3.y;
        *(uint16_t*)(Mo + (size_t)(cb + qr * 64 + r) * CC + mb + qc * 64 + 2 * p) =
            pack_e4m3x2(sx, sy);
        S[r][2 * p] = sx; S[r][2 * p + 1] = sy;
    }
    if (ii == jj) return;
    __syncthreads();
#pragma unroll
    for (int e = 0; e < 8; e++) {
        int idx = tid + e * 256;
        int m = idx >> 5, p = idx & 31;
        uint16_t v = pack_e4m3x2(S[2 * p][m], S[2 * p + 1][m]);
        *(uint16_t*)(Mo + (size_t)(mb + qc * 64 + m) * CC + cb + qr * 64 + 2 * p) = v;
    }
}

// ===========================================================================
// Kernel 5: GEMM2  S'[c,n] = sum_m Mb[c,m]*y8T[n,m]; fused epilogue:
//   tailor = 1/(N + tacc[c]);  out = x + gamma*tailor*(colsum + srn*S')
// ===========================================================================
__global__ void __launch_bounds__(256, 2) gemm2_mma(const float* __restrict__ x,
                                                    const float* __restrict__ gptr,
                                                    float* __restrict__ out) {
    extern __shared__ __align__(128) char dsm[];
    const uint32_t sb0 = smem_u32(dsm);
    const int tid = threadIdx.x, lane = tid & 31, warp = tid >> 5;
    const int wm = warp & 3, wn = warp >> 2;
    const int b = blockIdx.z, cb = blockIdx.y * 128, nb = blockIdx.x * 128;
    const uint8_t* A  = g_Mb8 + (size_t)(b * CC + cb) * CC;
    const uint8_t* Bp = g_y8T + ((size_t)b * NN + nb) * CC;

    float acc[2][8][4];
#pragma unroll
    for (int i = 0; i < 2; i++)
#pragma unroll
        for (int j = 0; j < 8; j++)
#pragma unroll
            for (int q = 0; q < 4; q++) acc[i][j][q] = 0.f;

    auto issue = [&](uint32_t sbase, int k0) {
#pragma unroll
        for (int i = 0; i < 8; i++) {
            int f = tid + i * 256;
            int half = f >> 10;
            int r = (f >> 3) & 127, ch = f & 7;
            const uint8_t* src =
                (half ? Bp + (size_t)r * CC : A + (size_t)r * CC) + k0 + ch * 16;
            cp16(sbase + half * STG_A + r * 144 + ch * 16, src);
        }
    };

    issue(sb0,            0); CP_COMMIT();
    issue(sb0 + STG_SZ, 128); CP_COMMIT();

    const int KT = 4;    // 512 / 128
    for (int kt = 0; kt < KT; kt++) {
        CP_WAIT1();
        __syncthreads();
        int nk = kt + 2;
        if (nk < KT) issue(sb0 + (nk % NSTAGE) * STG_SZ, nk * 128);
        CP_COMMIT();
        uint32_t s = sb0 + (kt % NSTAGE) * STG_SZ;
        compute_stage(s, s + STG_A, wm, wn, lane, acc);
    }

    float gamma = __ldg(gptr);
#pragma unroll
    for (int mt = 0; mt < 2; mt++) {
        int c0 = cb + wm * 32 + mt * 16 + (lane >> 2);
#pragma unroll
        for (int half = 0; half < 2; half++) {
            int c = c0 + half * 8;
            float tg = gamma / ((float)NN + g_tacc[b * CC + c]);
            const float* xrow = x   + ((size_t)b * CC + c) * NN;
            float*       orow = out + ((size_t)b * CC + c) * NN;
#pragma unroll
            for (int nt = 0; nt < 8; nt++) {
                int n = nb + wn * 64 + nt * 8 + 2 * (lane & 3);
                float Sx = acc[mt][nt][half * 2];
                float Sy = acc[mt][nt][half * 2 + 1];
                float2 cs = *(const float2*)(g_colsum + b * NN + n);
                float2 sr = *(const float2*)(g_srn    + b * NN + n);
                float2 xv = *(const float2*)(xrow + n);
                float2 o;
                o.x = fmaf(tg, fmaf(sr.x, Sx, cs.x), xv.x);
                o.y = fmaf(tg, fmaf(sr.y, Sy, cs.y), xv.y);
                *(float2*)(orow + n) = o;
            }
        }
    }
}

// ===========================================================================
extern "C" void kernel_launch(void* const* d_in, const int* in_sizes, int n_in,
                              void* d_out, int out_size) {
    const float* x     = (const float*)d_in[0];
    const float* gamma = (const float*)d_in[1];
    float* out = (float*)d_out;

    cudaFuncSetAttribute(gemm1_mma, cudaFuncAttributeMaxDynamicSharedMemorySize, SM_DYN);
    cudaFuncSetAttribute(gemm2_mma, cudaFuncAttributeMaxDynamicSharedMemorySize, SM_DYN);

    col_stats_kernel<<<(BB * NN) / 256, 256>>>(x);
    convert_kernel<<<dim3(NN / 64, CC / 64, BB), 256>>>(x);
    gemm1_mma<<<dim3(10, 4, BB), 256, SM_DYN>>>();
    reduce_mirror<<<dim3(4, 10, BB), 256>>>();
    gemm2_mma<<<dim3(NN / 128, CC / 128, BB), 256, SM_DYN>>>(x, gamma, out);
}

// round 16
// speedup vs baseline: 5.7591x; 1.0752x over previous
#include <cuda_runtime.h>
#include <cuda_bf16.h>
#include <cstdint>

#define BB 16
#define CC 512
#define NN 4096
#define EPSF 1e-6f

// ---------------- device scratch (allocation-free rule) ----------------
__device__ float g_srn   [BB * NN];
__device__ float g_colsum[BB * NN];
__device__ float g_tacc  [BB * CC];                 // tailor accumulators
__device__ uint8_t g_y8 [(size_t)BB * CC * NN];     // e4m3(x*srn) [b,c,n]
__device__ uint8_t g_y8T[(size_t)BB * NN * CC];     // e4m3(x*srn) [b,n,c]
__device__ uint8_t g_Mb8[(size_t)BB * CC * CC];     // e4m3(M)     [b,c,m]
__device__ __nv_bfloat16 g_Mp[(size_t)4 * BB * 10 * 16384];  // split-K partials (bf16)

// ---------------- helpers ----------------
__device__ __forceinline__ uint32_t smem_u32(const void* p) {
    uint32_t a;
    asm("{ .reg .u64 t; cvta.to.shared.u64 t, %1; cvt.u32.u64 %0, t; }" : "=r"(a) : "l"(p));
    return a;
}
__device__ __forceinline__ uint16_t pack_e4m3x2(float lo, float hi) {
    uint16_t r;
    asm("cvt.rn.satfinite.e4m3x2.f32 %0, %1, %2;" : "=h"(r) : "f"(hi), "f"(lo));
    return r;
}
__device__ __forceinline__ uint32_t pack_e4m3x4(float f0, float f1, float f2, float f3) {
    uint16_t lo = pack_e4m3x2(f0, f1);
    uint16_t hi = pack_e4m3x2(f2, f3);
    return (uint32_t)lo | ((uint32_t)hi << 16);
}
__device__ __forceinline__ uint32_t pack_bf16x2(float lo, float hi) {
    uint32_t r;
    asm("cvt.rn.bf16x2.f32 %0, %1, %2;" : "=r"(r) : "f"(hi), "f"(lo));
    return r;
}
__device__ __forceinline__ void ldsm_x4(uint32_t& r0, uint32_t& r1, uint32_t& r2,
                                        uint32_t& r3, uint32_t addr) {
    asm volatile("ldmatrix.sync.aligned.m8n8.x4.shared.b16 {%0,%1,%2,%3}, [%4];"
                 : "=r"(r0), "=r"(r1), "=r"(r2), "=r"(r3) : "r"(addr));
}
__device__ __forceinline__ void mma_fp8(float* c, const uint32_t* a,
                                        uint32_t b0, uint32_t b1) {
    asm volatile(
        "mma.sync.aligned.m16n8k32.row.col.f32.e4m3.e4m3.f32 "
        "{%0,%1,%2,%3}, {%4,%5,%6,%7}, {%8,%9}, {%0,%1,%2,%3};"
        : "+f"(c[0]), "+f"(c[1]), "+f"(c[2]), "+f"(c[3])
        : "r"(a[0]), "r"(a[1]), "r"(a[2]), "r"(a[3]), "r"(b0), "r"(b1));
}
__device__ __forceinline__ void cp16(uint32_t dst, const void* src) {
    asm volatile("cp.async.cg.shared.global [%0], [%1], 16;" :: "r"(dst), "l"(src));
}
#define CP_COMMIT() asm volatile("cp.async.commit_group;" ::: "memory")
#define CP_WAIT1()  asm volatile("cp.async.wait_group 1;"  ::: "memory")

// GEMM tiles 128x128, BK = 128 fp8 (128 B); smem row = 144 B
#define STG_A    18432u
#define STG_SZ   36864u
#define NSTAGE   3
#define SM_DYN   (NSTAGE * STG_SZ)

// prep smem: S[512][65] floats + aux
#define PREP_STRIDE 65
#define PREP_AUX    (512 * PREP_STRIDE)
#define PREP_SMEM   ((512 * PREP_STRIDE + 512 + 512 + 64 + 64) * 4)

// ===========================================================================
// Kernel 1: fused stats + convert. One CTA = full channel column x 64 n.
//   reads x once; writes y8, y8T, srn, colsum; atomicAdd tailor dots.
// grid (NN/64, BB), 512 threads.
// ===========================================================================
__global__ void __launch_bounds__(512) prep_kernel(const float* __restrict__ x) {
    extern __shared__ float PS[];
    float* S    = PS;                       // [512][65]
    float* ssp  = PS + PREP_AUX;            // [8][64]
    float* csp  = ssp + 512;                // [8][64]
    float* srnS = csp + 512;                // [64]
    float* wS   = srnS + 64;                // [64]

    const int b = blockIdx.y, n0 = blockIdx.x * 64;
    const int t = threadIdx.x;
    const float* xb = x + (size_t)b * CC * NN + n0;

    // ---- load 512x64 slab (float4, coalesced 256B rows) ----
#pragma unroll
    for (int i = 0; i < 16; i++) {
        int idx = t + i * 512;              // 0..8191
        int c = idx >> 4, q = idx & 15;
        float4 v = *(const float4*)(xb + (size_t)c * NN + q * 4);
        float* s = &S[c * PREP_STRIDE + q * 4];
        s[0] = v.x; s[1] = v.y; s[2] = v.z; s[3] = v.w;
    }
    __syncthreads();

    // ---- column stats: thread (n = t&63, chunk = t>>6) ----
    {
        int n = t & 63, ch = t >> 6;
        float ss = 0.f, cs = 0.f;
#pragma unroll 8
        for (int i = 0; i < 64; i++) {
            float v = S[(ch * 64 + i) * PREP_STRIDE + n];
            ss = fmaf(v, v, ss);
            cs += v;
        }
        ssp[ch * 64 + n] = ss;
        csp[ch * 64 + n] = cs;
    }
    __syncthreads();
    if (t < 64) {
        float ss = 0.f, cs = 0.f;
#pragma unroll
        for (int ch = 0; ch < 8; ch++) { ss += ssp[ch * 64 + t]; cs += csp[ch * 64 + t]; }
        float rn = rsqrtf(ss);
        float sr = sqrtf(rn);
        srnS[t] = sr;
        wS[t]   = rn * fmaf(cs, rn, EPSF);
        g_srn   [b * NN + n0 + t] = sr;
        g_colsum[b * NN + n0 + t] = cs;
    }
    __syncthreads();

    // ---- tailor partial: thread t = channel c; exact fp32 dot ----
    {
        float d = 0.f;
        const float* row = &S[t * PREP_STRIDE];
#pragma unroll 8
        for (int n = 0; n < 64; n++) d = fmaf(row[n], wS[n], d);
        atomicAdd(&g_tacc[b * CC + t], d);
    }

    // ---- y8 = e4m3(x*srn), [c][n] ----
#pragma unroll
    for (int i = 0; i < 16; i++) {
        int idx = t + i * 512;
        int c = idx >> 4, q = idx & 15;
        const float* s = &S[c * PREP_STRIDE + q * 4];
        const float* sr = &srnS[q * 4];
        *(uint32_t*)(g_y8 + (size_t)(b * CC + c) * NN + n0 + q * 4) =
            pack_e4m3x4(s[0] * sr[0], s[1] * sr[1], s[2] * sr[2], s[3] * sr[3]);
    }

    // ---- y8T = e4m3(x*srn), [n][c] (4-way smem conflict, coalesced 128B out) ----
#pragma unroll
    for (int i = 0; i < 16; i++) {
        int idx = t + i * 512;              // 0..8191
        int n = idx >> 7, c4 = (idx & 127) * 4;
        float sr = srnS[n];
        float y0 = S[(c4 + 0) * PREP_STRIDE + n] * sr;
        float y1 = S[(c4 + 1) * PREP_STRIDE + n] * sr;
        float y2 = S[(c4 + 2) * PREP_STRIDE + n] * sr;
        float y3 = S[(c4 + 3) * PREP_STRIDE + n] * sr;
        *(uint32_t*)(g_y8T + ((size_t)b * NN + n0 + n) * CC + c4) =
            pack_e4m3x4(y0, y1, y2, y3);
    }
}

// ===========================================================================
// Fragment loaders (fp8 K-major; k-step = 32 B)
// ===========================================================================
__device__ __forceinline__ void lda_frag(uint32_t a[2][4], uint32_t sa,
                                         int wm, int lane, int ks) {
    const uint32_t lrow = lane & 15, lch = (lane >> 4) << 4;
#pragma unroll
    for (int mt = 0; mt < 2; mt++)
        ldsm_x4(a[mt][0], a[mt][1], a[mt][2], a[mt][3],
                sa + (wm * 32 + mt * 16 + lrow) * 144 + ks * 32 + lch);
}
__device__ __forceinline__ void ldb_nt(uint32_t bf[4], uint32_t sb,
                                       int wn, int lane, int ks, int p) {
    const uint32_t lrow = lane & 15, lch = (lane >> 4) << 4;
    ldsm_x4(bf[0], bf[1], bf[2], bf[3],
            sb + (wn * 64 + p * 16 + lrow) * 144 + ks * 32 + lch);
}
__device__ __forceinline__ void mma_group(float acc[2][8][4], uint32_t a[2][4],
                                          uint32_t bf[4], int p) {
#pragma unroll
    for (int mt = 0; mt < 2; mt++) {
        mma_fp8(acc[mt][2 * p],     a[mt], bf[0], bf[2]);
        mma_fp8(acc[mt][2 * p + 1], a[mt], bf[1], bf[3]);
    }
}
__device__ __forceinline__ void compute_stage(uint32_t sa, uint32_t sbB,
                                              int wm, int wn, int lane,
                                              float acc[2][8][4]) {
    uint32_t a[2][2][4], bf[2][4];
    lda_frag(a[0], sa, wm, lane, 0);
    ldb_nt(bf[0], sbB, wn, lane, 0, 0);
#pragma unroll
    for (int ks = 0; ks < 4; ks++) {
#pragma unroll
        for (int p = 0; p < 4; p++) {
            int cur = (ks * 4 + p) & 1, nxt = cur ^ 1;
            if (p < 3) ldb_nt(bf[nxt], sbB, wn, lane, ks, p + 1);
            else if (ks < 3) {
                ldb_nt(bf[nxt], sbB, wn, lane, ks + 1, 0);
                lda_frag(a[(ks + 1) & 1], sa, wm, lane, ks + 1);
            }
            mma_group(acc, a[ks & 1], bf[cur], p);
        }
    }
}

// ===========================================================================
// Kernel 2: GEMM1 (symmetric, split-K=4)  M = y.y^T upper-tri tiles, fp8
// -> bf16 partials
// ===========================================================================
__global__ void __launch_bounds__(256, 2) gemm1_mma() {
    extern __shared__ __align__(128) char dsm[];
    const uint32_t sb0 = smem_u32(dsm);
    const int tid = threadIdx.x, lane = tid & 31, warp = tid >> 5;
    const int wm = warp & 3, wn = warp >> 2;
    const int TI[10] = {0,0,0,0,1,1,1,2,2,3};
    const int TJ[10] = {0,1,2,3,1,2,3,2,3,3};
    const int tile = blockIdx.x, sp = blockIdx.y, b = blockIdx.z;
    const int cb = TI[tile] * 128, mb = TJ[tile] * 128;
    const int kbase = sp * 1024;
    const uint8_t* A  = g_y8 + (size_t)(b * CC + cb) * NN;
    const uint8_t* Bp = g_y8 + (size_t)(b * CC + mb) * NN;

    float acc[2][8][4];
#pragma unroll
    for (int i = 0; i < 2; i++)
#pragma unroll
        for (int j = 0; j < 8; j++)
#pragma unroll
            for (int q = 0; q < 4; q++) acc[i][j][q] = 0.f;

    auto issue = [&](uint32_t sbase, int k0) {
#pragma unroll
        for (int i = 0; i < 8; i++) {
            int f = tid + i * 256;
            int half = f >> 10;
            int r = (f >> 3) & 127, ch = f & 7;
            const uint8_t* src =
                (half ? Bp + (size_t)r * NN : A + (size_t)r * NN) + k0 + ch * 16;
            cp16(sbase + half * STG_A + r * 144 + ch * 16, src);
        }
    };

    issue(sb0,          kbase);       CP_COMMIT();
    issue(sb0 + STG_SZ, kbase + 128); CP_COMMIT();

    const int KT = 8;
    for (int kt = 0; kt < KT; kt++) {
        CP_WAIT1();
        __syncthreads();
        int nk = kt + 2;
        if (nk < KT) issue(sb0 + (nk % NSTAGE) * STG_SZ, kbase + nk * 128);
        CP_COMMIT();
        uint32_t s = sb0 + (kt % NSTAGE) * STG_SZ;
        compute_stage(s, s + STG_A, wm, wn, lane, acc);
    }

    __nv_bfloat16* Mp = g_Mp + (((size_t)sp * BB + b) * 10 + tile) * 16384;
#pragma unroll
    for (int mt = 0; mt < 2; mt++) {
        int r0 = wm * 32 + mt * 16 + (lane >> 2);
#pragma unroll
        for (int nt = 0; nt < 8; nt++) {
            int col = wn * 64 + nt * 8 + 2 * (lane & 3);
            *(uint32_t*)(Mp + r0 * 128 + col) =
                pack_bf16x2(acc[mt][nt][0], acc[mt][nt][1]);
            *(uint32_t*)(Mp + (r0 + 8) * 128 + col) =
                pack_bf16x2(acc[mt][nt][2], acc[mt][nt][3]);
        }
    }
}

// ===========================================================================
// Kernel 3: reduce bf16 split-K partials -> fp8 Mb (+ mirrored tile)
// ===========================================================================
__global__ void __launch_bounds__(256) reduce_mirror() {
    __shared__ float S[64][65];
    const int TI[10] = {0,0,0,0,1,1,1,2,2,3};
    const int TJ[10] = {0,1,2,3,1,2,3,2,3,3};
    const int q = blockIdx.x, t = blockIdx.y, b = blockIdx.z;
    const int ii = TI[t], jj = TJ[t];
    const int qr = q >> 1, qc = q & 1;
    const int tid = threadIdx.x;
    const size_t spstride = (size_t)BB * 10 * 16384;
    const __nv_bfloat16* base = g_Mp + ((size_t)b * 10 + t) * 16384;
    uint8_t* Mo = g_Mb8 + (size_t)b * CC * CC;
    const int cb = ii * 128, mb = jj * 128;

#pragma unroll
    for (int e = 0; e < 8; e++) {
        int idx = tid + e * 256;
        int r = idx >> 5, p = idx & 31;
        int off = (qr * 64 + r) * 128 + qc * 64 + 2 * p;
        float2 s0 = __bfloat1622float2(*(const __nv_bfloat162*)(base + off));
        float2 s1 = __bfloat1622float2(*(const __nv_bfloat162*)(base + spstride + off));
        float2 s2 = __bfloat1622float2(*(const __nv_bfloat162*)(base + 2 * spstride + off));
        float2 s3 = __bfloat1622float2(*(const __nv_bfloat162*)(base + 3 * spstride + off));
        float sx = s0.x + s1.x + s2.x + s3.x;
        float sy = s0.y + s1.y + s2.y + s3.y;
        *(uint16_t*)(Mo + (size_t)(cb + qr * 64 + r) * CC + mb + qc * 64 + 2 * p) =
            pack_e4m3x2(sx, sy);
        S[r][2 * p] = sx; S[r][2 * p + 1] = sy;
    }
    if (ii == jj) return;
    __syncthreads();
#pragma unroll
    for (int e = 0; e < 8; e++) {
        int idx = tid + e * 256;
        int m = idx >> 5, p = idx & 31;
        uint16_t v = pack_e4m3x2(S[2 * p][m], S[2 * p + 1][m]);
        *(uint16_t*)(Mo + (size_t)(mb + qc * 64 + m) * CC + cb + qr * 64 + 2 * p) = v;
    }
}

// ===========================================================================
// Kernel 4: GEMM2  S'[c,n] = sum_m Mb[c,m]*y8T[n,m]; fused epilogue:
//   tailor = 1/(N + tacc[c]);  out = x + gamma*tailor*(colsum + srn*S')
// ===========================================================================
__global__ void __launch_bounds__(256, 2) gemm2_mma(const float* __restrict__ x,
                                                    const float* __restrict__ gptr,
                                                    float* __restrict__ out) {
    extern __shared__ __align__(128) char dsm[];
    const uint32_t sb0 = smem_u32(dsm);
    const int tid = threadIdx.x, lane = tid & 31, warp = tid >> 5;
    const int wm = warp & 3, wn = warp >> 2;
    const int b = blockIdx.z, cb = blockIdx.y * 128, nb = blockIdx.x * 128;
    const uint8_t* A  = g_Mb8 + (size_t)(b * CC + cb) * CC;
    const uint8_t* Bp = g_y8T + ((size_t)b * NN + nb) * CC;

    float acc[2][8][4];
#pragma unroll
    for (int i = 0; i < 2; i++)
#pragma unroll
        for (int j = 0; j < 8; j++)
#pragma unroll
            for (int q = 0; q < 4; q++) acc[i][j][q] = 0.f;

    auto issue = [&](uint32_t sbase, int k0) {
#pragma unroll
        for (int i = 0; i < 8; i++) {
            int f = tid + i * 256;
            int half = f >> 10;
            int r = (f >> 3) & 127, ch = f & 7;
            const uint8_t* src =
                (half ? Bp + (size_t)r * CC : A + (size_t)r * CC) + k0 + ch * 16;
            cp16(sbase + half * STG_A + r * 144 + ch * 16, src);
        }
    };

    issue(sb0,            0); CP_COMMIT();
    issue(sb0 + STG_SZ, 128); CP_COMMIT();

    const int KT = 4;
    for (int kt = 0; kt < KT; kt++) {
        CP_WAIT1();
        __syncthreads();
        int nk = kt + 2;
        if (nk < KT) issue(sb0 + (nk % NSTAGE) * STG_SZ, nk * 128);
        CP_COMMIT();
        uint32_t s = sb0 + (kt % NSTAGE) * STG_SZ;
        compute_stage(s, s + STG_A, wm, wn, lane, acc);
    }

    float gamma = __ldg(gptr);
#pragma unroll
    for (int mt = 0; mt < 2; mt++) {
        int c0 = cb + wm * 32 + mt * 16 + (lane >> 2);
#pragma unroll
        for (int half = 0; half < 2; half++) {
            int c = c0 + half * 8;
            float tg = gamma / ((float)NN + g_tacc[b * CC + c]);
            const float* xrow = x   + ((size_t)b * CC + c) * NN;
            float*       orow = out + ((size_t)b * CC + c) * NN;
#pragma unroll
            for (int nt = 0; nt < 8; nt++) {
                int n = nb + wn * 64 + nt * 8 + 2 * (lane & 3);
                float Sx = acc[mt][nt][half * 2];
                float Sy = acc[mt][nt][half * 2 + 1];
                float2 cs = *(const float2*)(g_colsum + b * NN + n);
                float2 sr = *(const float2*)(g_srn    + b * NN + n);
                float2 xv = *(const float2*)(xrow + n);
                float2 o;
                o.x = fmaf(tg, fmaf(sr.x, Sx, cs.x), xv.x);
                o.y = fmaf(tg, fmaf(sr.y, Sy, cs.y), xv.y);
                *(float2*)(orow + n) = o;
            }
        }
    }
}

// ===========================================================================
extern "C" void kernel_launch(void* const* d_in, const int* in_sizes, int n_in,
                              void* d_out, int out_size) {
    const float* x     = (const float*)d_in[0];
    const float* gamma = (const float*)d_in[1];
    float* out = (float*)d_out;

    cudaFuncSetAttribute(prep_kernel, cudaFuncAttributeMaxDynamicSharedMemorySize, PREP_SMEM);
    cudaFuncSetAttribute(gemm1_mma,  cudaFuncAttributeMaxDynamicSharedMemorySize, SM_DYN);
    cudaFuncSetAttribute(gemm2_mma,  cudaFuncAttributeMaxDynamicSharedMemorySize, SM_DYN);

    void* taccPtr = nullptr;
    cudaGetSymbolAddress(&taccPtr, g_tacc);
    cudaMemsetAsync(taccPtr, 0, BB * CC * sizeof(float));

    prep_kernel<<<dim3(NN / 64, BB), 512, PREP_SMEM>>>(x);
    gemm1_mma<<<dim3(10, 4, BB), 256, SM_DYN>>>();
    reduce_mirror<<<dim3(4, 10, BB), 256>>>();
    gemm2_mma<<<dim3(NN / 128, CC / 128, BB), 256, SM_DYN>>>(x, gamma, out);
}